// round 1
// baseline (speedup 1.0000x reference)
#include <cuda_runtime.h>
#include <math.h>

#define FDIM 512
#define DDIM 128
#define MSZ  8
#define NMAX 50048
#define EPSF 1e-5f

// Scratch (allocation-free rule: device globals)
__device__ float g_x[(size_t)NMAX * DDIM];   // encoded node features, clipped
__device__ float g_At[DDIM * DDIM];          // A^T : At[j*128+k] = A[k][j]
__device__ float g_Bt[DDIM * DDIM];          // B^T

// ---------------------------------------------------------------------------
// Kernel 1: combine Chebyshev weights into A = W0 + W1/7 - 47/49 W2,
//           B = -W1/7 + 12/49 W2 (closed form of K=3 Cheb on 8-clique).
// ---------------------------------------------------------------------------
__global__ void prep_kernel(const float* __restrict__ chebW) {
    int idx = blockIdx.x * blockDim.x + threadIdx.x;
    if (idx < DDIM * DDIM) {
        int k = idx >> 7;     // input dim d
        int j = idx & 127;    // output dim c
        float w0 = chebW[idx];
        float w1 = chebW[DDIM * DDIM + idx];
        float w2 = chebW[2 * DDIM * DDIM + idx];
        g_At[j * DDIM + k] = w0 + w1 * (1.0f / 7.0f) - w2 * (47.0f / 49.0f);
        g_Bt[j * DDIM + k] = -w1 * (1.0f / 7.0f) + w2 * (12.0f / 49.0f);
    }
}

// ---------------------------------------------------------------------------
// Kernel 2: encoder  x = clip(pos @ W_enc + b, -1, 1)   [N,512]@[512,128]
// 128x128 tile, BK=16, double-buffered, 256 threads, 8x8 micro-tile.
// ---------------------------------------------------------------------------
__global__ __launch_bounds__(256, 2)
void encoder_kernel(const float* __restrict__ pos, const float* __restrict__ W,
                    const float* __restrict__ bias, int N) {
    __shared__ __align__(16) float As[2][16][128];
    __shared__ __align__(16) float Bs[2][16][128];

    const int t   = threadIdx.x;
    const int m0  = blockIdx.x * 128;
    const int lm  = t & 127;          // A loader: row in tile
    const int lkh = t >> 7;           // A loader: 0/1 (k-group of 8)
    const int lk  = t >> 4;           // B loader: k row 0..15
    const int ln  = (t & 15) * 8;     // B loader: col
    const int tx  = t & 15, ty = t >> 4;

    float acc[8][8];
#pragma unroll
    for (int i = 0; i < 8; i++)
#pragma unroll
        for (int j = 0; j < 8; j++) acc[i][j] = 0.0f;

    const bool arow_ok = (m0 + lm) < N;
    const float* aptr = pos + (long)(m0 + lm) * FDIM + lkh * 8;

    float4 pa0, pa1, pb0, pb1;
    // prologue: load k-tile 0
    if (arow_ok) {
        pa0 = *(const float4*)(aptr);
        pa1 = *(const float4*)(aptr + 4);
    } else {
        pa0 = make_float4(0, 0, 0, 0);
        pa1 = make_float4(0, 0, 0, 0);
    }
    {
        const float* bp = W + lk * 128 + ln;
        pb0 = *(const float4*)(bp);
        pb1 = *(const float4*)(bp + 4);
    }
    // store stage 0
    {
        As[0][lkh * 8 + 0][lm] = pa0.x; As[0][lkh * 8 + 1][lm] = pa0.y;
        As[0][lkh * 8 + 2][lm] = pa0.z; As[0][lkh * 8 + 3][lm] = pa0.w;
        As[0][lkh * 8 + 4][lm] = pa1.x; As[0][lkh * 8 + 5][lm] = pa1.y;
        As[0][lkh * 8 + 6][lm] = pa1.z; As[0][lkh * 8 + 7][lm] = pa1.w;
        *(float4*)&Bs[0][lk][ln]     = pb0;
        *(float4*)&Bs[0][lk][ln + 4] = pb1;
    }
    __syncthreads();

    for (int kt = 0; kt < 32; kt++) {
        const int s = kt & 1;
        if (kt < 31) {
            const float* ap = aptr + (kt + 1) * 16;
            if (arow_ok) {
                pa0 = *(const float4*)(ap);
                pa1 = *(const float4*)(ap + 4);
            } else {
                pa0 = make_float4(0, 0, 0, 0);
                pa1 = make_float4(0, 0, 0, 0);
            }
            const float* bp = W + ((kt + 1) * 16 + lk) * 128 + ln;
            pb0 = *(const float4*)(bp);
            pb1 = *(const float4*)(bp + 4);
        }
#pragma unroll
        for (int kk = 0; kk < 16; kk++) {
            float4 a0 = *(const float4*)&As[s][kk][ty * 8];
            float4 a1 = *(const float4*)&As[s][kk][ty * 8 + 4];
            float4 b0 = *(const float4*)&Bs[s][kk][tx * 8];
            float4 b1 = *(const float4*)&Bs[s][kk][tx * 8 + 4];
            float av[8] = {a0.x, a0.y, a0.z, a0.w, a1.x, a1.y, a1.z, a1.w};
            float bv[8] = {b0.x, b0.y, b0.z, b0.w, b1.x, b1.y, b1.z, b1.w};
#pragma unroll
            for (int i = 0; i < 8; i++)
#pragma unroll
                for (int j = 0; j < 8; j++) acc[i][j] += av[i] * bv[j];
        }
        if (kt < 31) {
            const int s2 = s ^ 1;
            As[s2][lkh * 8 + 0][lm] = pa0.x; As[s2][lkh * 8 + 1][lm] = pa0.y;
            As[s2][lkh * 8 + 2][lm] = pa0.z; As[s2][lkh * 8 + 3][lm] = pa0.w;
            As[s2][lkh * 8 + 4][lm] = pa1.x; As[s2][lkh * 8 + 5][lm] = pa1.y;
            As[s2][lkh * 8 + 6][lm] = pa1.z; As[s2][lkh * 8 + 7][lm] = pa1.w;
            *(float4*)&Bs[s2][lk][ln]     = pb0;
            *(float4*)&Bs[s2][lk][ln + 4] = pb1;
            __syncthreads();
        }
    }

    // epilogue: bias + hardtanh + store
    float bj[8];
#pragma unroll
    for (int j = 0; j < 8; j++) bj[j] = bias[tx * 8 + j];
#pragma unroll
    for (int i = 0; i < 8; i++) {
        int row = m0 + ty * 8 + i;
        if (row < N) {
            float o[8];
#pragma unroll
            for (int j = 0; j < 8; j++) {
                float v = acc[i][j] + bj[j];
                o[j] = fminf(1.0f, fmaxf(-1.0f, v));
            }
            float4* dst = (float4*)(g_x + (long)row * 128 + tx * 8);
            dst[0] = make_float4(o[0], o[1], o[2], o[3]);
            dst[1] = make_float4(o[4], o[5], o[6], o[7]);
        }
    }
}

// ---------------------------------------------------------------------------
// Kernel 3: fused per-hyperedge pipeline.
// 128 threads = 128 channels; each block processes 4 edges per iteration.
// Thread c: gathers column c of the 8 member rows, does GraphNorm in
// registers, writes normalized g + colsum S to smem; then GEMM
// out = g@A + S@B with A/B rows register-reused across the 4 edges
// (A,B stay L1-resident); then hardtanh + max/min/L2 pooling + linear
// + sigmoid, reduced warp-wise.
// ---------------------------------------------------------------------------
__global__ __launch_bounds__(128, 4)
void edge_kernel(const int* __restrict__ members,
                 const float* __restrict__ gamma_, const float* __restrict__ beta_,
                 const float* __restrict__ alpha_, const float* __restrict__ chebb,
                 const float* __restrict__ linW, const float* __restrict__ linb,
                 float* __restrict__ out, int E) {
    __shared__ __align__(16) float gsh[4][8][128];
    __shared__ __align__(16) float Ssh[4][128];
    __shared__ float wred[4][4];   // [warp][e4]

    const int c = threadIdx.x;
    const int warp = c >> 5, lane = c & 31;
    const float ga = gamma_[c], be = beta_[c], al = alpha_[c], cb = chebb[c];
    const float lw0 = linW[c], lw1 = linW[128 + c], lb = linb[0];
    const int nquads = (E + 3) >> 2;

    for (int q = blockIdx.x; q < nquads; q += gridDim.x) {
        // ---- gather + GraphNorm (per-channel, fully in-thread) ----
#pragma unroll
        for (int e4 = 0; e4 < 4; e4++) {
            int e = q * 4 + e4;
            if (e < E) {
                float xv[8];
#pragma unroll
                for (int i = 0; i < 8; i++) {
                    int node = __ldg(&members[e * 8 + i]);
                    xv[i] = __ldcs(&g_x[(long)node * 128 + c]);
                }
                float mean = 0.0f;
#pragma unroll
                for (int i = 0; i < 8; i++) mean += xv[i];
                mean *= 0.125f;
                float am = al * mean;
                float ct[8];
                float var = 0.0f;
#pragma unroll
                for (int i = 0; i < 8; i++) { ct[i] = xv[i] - am; var += ct[i] * ct[i]; }
                var *= 0.125f;
                float inv = ga / sqrtf(var + EPSF);
                float S = 0.0f;
#pragma unroll
                for (int i = 0; i < 8; i++) {
                    float g = ct[i] * inv + be;
                    gsh[e4][i][c] = g;
                    S += g;
                }
                Ssh[e4][c] = S;
            }
        }
        __syncthreads();

        // ---- GEMM: out[e4][i] = g[e4][i] . A[:,c]  ;  sb[e4] = S[e4] . B[:,c]
        float acc[4][8];
        float sb[4];
#pragma unroll
        for (int e4 = 0; e4 < 4; e4++) {
            sb[e4] = 0.0f;
#pragma unroll
            for (int i = 0; i < 8; i++) acc[e4][i] = 0.0f;
        }
        const float4* Ar = (const float4*)(g_At + c * 128);
        const float4* Br = (const float4*)(g_Bt + c * 128);
#pragma unroll 2
        for (int k4 = 0; k4 < 32; k4++) {
            float4 av = __ldg(&Ar[k4]);
            float4 bv = __ldg(&Br[k4]);
#pragma unroll
            for (int e4 = 0; e4 < 4; e4++) {
                float4 sv = *(const float4*)&Ssh[e4][k4 * 4];
                sb[e4] += bv.x * sv.x + bv.y * sv.y + bv.z * sv.z + bv.w * sv.w;
#pragma unroll
                for (int i = 0; i < 8; i++) {
                    float4 gv = *(const float4*)&gsh[e4][i][k4 * 4];
                    acc[e4][i] += av.x * gv.x + av.y * gv.y + av.z * gv.z + av.w * gv.w;
                }
            }
        }

        // ---- hardtanh + pooling + linear head contribution ----
        float contrib[4];
#pragma unroll
        for (int e4 = 0; e4 < 4; e4++) {
            float hmax = -2.0f, hmin = 2.0f, ss = 0.0f;
#pragma unroll
            for (int i = 0; i < 8; i++) {
                float h = acc[e4][i] + sb[e4] + cb;
                h = fminf(1.0f, fmaxf(-1.0f, h));
                hmax = fmaxf(hmax, h);
                hmin = fminf(hmin, h);
                ss += h * h;
            }
            contrib[e4] = (hmax - hmin) * lw0 + sqrtf(ss * 0.125f) * lw1;
        }
#pragma unroll
        for (int e4 = 0; e4 < 4; e4++) {
            float v = contrib[e4];
#pragma unroll
            for (int off = 16; off; off >>= 1)
                v += __shfl_xor_sync(0xffffffffu, v, off);
            if (lane == 0) wred[warp][e4] = v;
        }
        __syncthreads();
        if (c < 4) {
            int e = q * 4 + c;
            if (e < E) {
                float logit = wred[0][c] + wred[1][c] + wred[2][c] + wred[3][c] + lb;
                out[e] = 1.0f / (1.0f + expf(-logit));
            }
        }
        __syncthreads();   // protect gsh/Ssh/wred before next iteration
    }
}

// ---------------------------------------------------------------------------
extern "C" void kernel_launch(void* const* d_in, const int* in_sizes, int n_in,
                              void* d_out, int out_size) {
    const float* pos   = (const float*)d_in[0];
    const float* Wenc  = (const float*)d_in[1];
    const float* benc  = (const float*)d_in[2];
    const float* gam   = (const float*)d_in[3];
    const float* bet   = (const float*)d_in[4];
    const float* alp   = (const float*)d_in[5];
    const float* chebW = (const float*)d_in[6];
    const float* chebb = (const float*)d_in[7];
    const float* linW  = (const float*)d_in[8];
    const float* linb  = (const float*)d_in[9];
    const int*   membs = (const int*)d_in[10];
    // d_in[11] edge_index, d_in[12] batch: structure is known analytically.

    int N = in_sizes[0] / FDIM;     // 50000
    int E = in_sizes[10] / MSZ;     // 20000

    prep_kernel<<<(DDIM * DDIM + 255) / 256, 256>>>(chebW);
    encoder_kernel<<<(N + 127) / 128, 256>>>(pos, Wenc, benc, N);

    int nquads = (E + 3) / 4;
    int grid = 592;                 // 4 blocks/SM on 148 SMs
    if (grid > nquads) grid = nquads;
    edge_kernel<<<grid, 128>>>(membs, gam, bet, alp, chebb, linW, linb,
                               (float*)d_out, E);
}

// round 2
// speedup vs baseline: 2.8955x; 2.8955x over previous
#include <cuda_runtime.h>
#include <math.h>

#define FDIM 512
#define DDIM 128
#define NMAX 50048
#define EPSF 1e-5f

// Scratch (allocation-free rule: device globals)
__device__ float g_x[(size_t)NMAX * DDIM];   // encoded node features
__device__ float g_A[DDIM * DDIM];           // combined Cheb matrix A [d][c]
__device__ float g_B[DDIM * DDIM];           // combined Cheb matrix B [d][c]

__device__ __forceinline__ unsigned f2tf(float x) {
    unsigned r; asm("cvt.rna.tf32.f32 %0, %1;" : "=r"(r) : "f"(x)); return r;
}
__device__ __forceinline__ void mma8(float* c, unsigned a0, unsigned a1,
                                     unsigned a2, unsigned a3,
                                     unsigned b0, unsigned b1) {
    asm volatile(
        "mma.sync.aligned.m16n8k8.row.col.f32.tf32.tf32.f32 "
        "{%0,%1,%2,%3},{%4,%5,%6,%7},{%8,%9},{%0,%1,%2,%3};"
        : "+f"(c[0]), "+f"(c[1]), "+f"(c[2]), "+f"(c[3])
        : "r"(a0), "r"(a1), "r"(a2), "r"(a3), "r"(b0), "r"(b1));
}
__device__ __forceinline__ float clipf(float v) {
    return fminf(1.0f, fmaxf(-1.0f, v));
}

// ---------------------------------------------------------------------------
// Kernel 1: combine Chebyshev weights (closed form of K=3 Cheb on 8-clique):
//   A = W0 + W1/7 - 47/49 W2 ,  B = -W1/7 + 12/49 W2   (natural [d][c] layout)
// ---------------------------------------------------------------------------
__global__ void prep_kernel(const float* __restrict__ chebW) {
    int idx = blockIdx.x * blockDim.x + threadIdx.x;
    if (idx < DDIM * DDIM) {
        float w0 = chebW[idx];
        float w1 = chebW[DDIM * DDIM + idx];
        float w2 = chebW[2 * DDIM * DDIM + idx];
        g_A[idx] = w0 + w1 * (1.0f / 7.0f) - w2 * (47.0f / 49.0f);
        g_B[idx] = -w1 * (1.0f / 7.0f) + w2 * (12.0f / 49.0f);
    }
}

// ---------------------------------------------------------------------------
// Kernel 2: encoder  x = clip(pos @ W_enc + b, -1, 1) via tf32 MMA.
// Block tile 128x128, BK=16 double buffered, 8 warps (4x2), warp tile 32x64.
// A smem: [row][k] stride 20 (conflict-free stores + frag reads).
// B smem: [k][n] with XOR-8(k&3) swizzle (conflict-free frag reads).
// ---------------------------------------------------------------------------
__global__ __launch_bounds__(256, 2)
void encoder_mma(const float* __restrict__ pos, const float* __restrict__ W,
                 const float* __restrict__ bias, int N) {
    __shared__ unsigned As[2][128 * 20];
    __shared__ unsigned Bs[2][16 * 128];

    const int t = threadIdx.x;
    const int m0 = blockIdx.x * 128;
    const int lane = t & 31, w = t >> 5;
    const int wy = w >> 1, wx = w & 1;
    const int lm = lane >> 2, lk = lane & 3;

    // A loader: thread -> (row am, k-half aq)
    const int am = t >> 1, aq = t & 1;
    const bool aok = (m0 + am) < N;
    const float* ap = pos + (size_t)(m0 + am) * FDIM + aq * 8;
    // B loader: thread -> (k-row bk, col group bq)
    const int bk = t >> 4, bq = t & 15;

    float acc[2][8][4];
#pragma unroll
    for (int mf = 0; mf < 2; mf++)
#pragma unroll
        for (int nf = 0; nf < 8; nf++)
#pragma unroll
            for (int r = 0; r < 4; r++) acc[mf][nf][r] = 0.0f;

    float4 pa0, pa1, pb0, pb1;
    // prologue: load k-tile 0
    if (aok) { pa0 = *(const float4*)(ap); pa1 = *(const float4*)(ap + 4); }
    else     { pa0 = make_float4(0,0,0,0); pa1 = make_float4(0,0,0,0); }
    {
        const float* bp = W + bk * 128 + bq * 8;
        pb0 = *(const float4*)(bp);
        pb1 = *(const float4*)(bp + 4);
    }
    // store stage 0
    {
        uint4 ua0 = make_uint4(f2tf(pa0.x), f2tf(pa0.y), f2tf(pa0.z), f2tf(pa0.w));
        uint4 ua1 = make_uint4(f2tf(pa1.x), f2tf(pa1.y), f2tf(pa1.z), f2tf(pa1.w));
        *(uint4*)&As[0][am * 20 + aq * 8]     = ua0;
        *(uint4*)&As[0][am * 20 + aq * 8 + 4] = ua1;
        int n = (bq * 8) ^ (8 * (bk & 3));
        uint4 ub0 = make_uint4(f2tf(pb0.x), f2tf(pb0.y), f2tf(pb0.z), f2tf(pb0.w));
        uint4 ub1 = make_uint4(f2tf(pb1.x), f2tf(pb1.y), f2tf(pb1.z), f2tf(pb1.w));
        *(uint4*)&Bs[0][bk * 128 + n]     = ub0;
        *(uint4*)&Bs[0][bk * 128 + n + 4] = ub1;
    }
    __syncthreads();

    for (int kt = 0; kt < 32; kt++) {
        const int s = kt & 1;
        if (kt < 31) {
            const float* a2p = ap + (kt + 1) * 16;
            if (aok) { pa0 = *(const float4*)(a2p); pa1 = *(const float4*)(a2p + 4); }
            else     { pa0 = make_float4(0,0,0,0);  pa1 = make_float4(0,0,0,0); }
            const float* bp = W + ((kt + 1) * 16 + bk) * 128 + bq * 8;
            pb0 = *(const float4*)(bp);
            pb1 = *(const float4*)(bp + 4);
        }
#pragma unroll
        for (int kh = 0; kh < 2; kh++) {
            const int k0 = kh * 8;
            unsigned a[2][4], b[8][2];
#pragma unroll
            for (int mf = 0; mf < 2; mf++) {
                int rb = wy * 32 + mf * 16;
                a[mf][0] = As[s][(rb + lm) * 20 + k0 + lk];
                a[mf][1] = As[s][(rb + lm + 8) * 20 + k0 + lk];
                a[mf][2] = As[s][(rb + lm) * 20 + k0 + lk + 4];
                a[mf][3] = As[s][(rb + lm + 8) * 20 + k0 + lk + 4];
            }
#pragma unroll
            for (int nf = 0; nf < 8; nf++) {
                int cb = wx * 64 + nf * 8;
                b[nf][0] = Bs[s][(k0 + lk) * 128 + ((cb + lm) ^ (8 * lk))];
                b[nf][1] = Bs[s][(k0 + lk + 4) * 128 + ((cb + lm) ^ (8 * lk))];
            }
#pragma unroll
            for (int mf = 0; mf < 2; mf++)
#pragma unroll
                for (int nf = 0; nf < 8; nf++)
                    mma8(acc[mf][nf], a[mf][0], a[mf][1], a[mf][2], a[mf][3],
                         b[nf][0], b[nf][1]);
        }
        if (kt < 31) {
            const int s2 = s ^ 1;
            uint4 ua0 = make_uint4(f2tf(pa0.x), f2tf(pa0.y), f2tf(pa0.z), f2tf(pa0.w));
            uint4 ua1 = make_uint4(f2tf(pa1.x), f2tf(pa1.y), f2tf(pa1.z), f2tf(pa1.w));
            *(uint4*)&As[s2][am * 20 + aq * 8]     = ua0;
            *(uint4*)&As[s2][am * 20 + aq * 8 + 4] = ua1;
            int n = (bq * 8) ^ (8 * (bk & 3));
            uint4 ub0 = make_uint4(f2tf(pb0.x), f2tf(pb0.y), f2tf(pb0.z), f2tf(pb0.w));
            uint4 ub1 = make_uint4(f2tf(pb1.x), f2tf(pb1.y), f2tf(pb1.z), f2tf(pb1.w));
            *(uint4*)&Bs[s2][bk * 128 + n]     = ub0;
            *(uint4*)&Bs[s2][bk * 128 + n + 4] = ub1;
            __syncthreads();
        }
    }

    // epilogue: bias + hardtanh + store to g_x
#pragma unroll
    for (int mf = 0; mf < 2; mf++) {
        int r0 = m0 + wy * 32 + mf * 16 + lm;
#pragma unroll
        for (int nf = 0; nf < 8; nf++) {
            int c = wx * 64 + nf * 8 + 2 * lk;
            float b0 = __ldg(bias + c), b1 = __ldg(bias + c + 1);
            if (r0 < N) {
                float2 v;
                v.x = clipf(acc[mf][nf][0] + b0);
                v.y = clipf(acc[mf][nf][1] + b1);
                *(float2*)&g_x[(size_t)r0 * 128 + c] = v;
            }
            if (r0 + 8 < N) {
                float2 v;
                v.x = clipf(acc[mf][nf][2] + b0);
                v.y = clipf(acc[mf][nf][3] + b1);
                *(float2*)&g_x[(size_t)(r0 + 8) * 128 + c] = v;
            }
        }
    }
}

// ---------------------------------------------------------------------------
// Kernel 3: fused per-hyperedge pipeline, 16 edges per iteration via tf32 MMA.
// smem layout (dynamic, 218368 B):
//   Acs  unsigned[16384]  @0       : Cheb A, [d][c] XOR-8(d&3) swizzle
//   Bcs  unsigned[16384]  @65536   : Cheb B, same layout
//   Gs   unsigned[128*132]@131072  : g row-major [row][d], stride 132
//   Hs   float  [128*136] @131072  : (union w/ Gs) h row-major, stride 136
//   Ssm  unsigned[16*132] @200704  : S row-major [e][d], stride 132
//   Qsm  float  [16*136]  @209408  : q = S@B + chebb
//   red  float  [16*4]    @218112
// ---------------------------------------------------------------------------
#define ESMEM 218368

__global__ __launch_bounds__(256, 1)
void edge_mma(const int* __restrict__ members,
              const float* __restrict__ gamma_, const float* __restrict__ beta_,
              const float* __restrict__ alpha_, const float* __restrict__ chebb,
              const float* __restrict__ linW, const float* __restrict__ linb,
              float* __restrict__ out, int E) {
    extern __shared__ unsigned char esm[];
    unsigned* Acs = (unsigned*)esm;
    unsigned* Bcs = (unsigned*)(esm + 65536);
    unsigned* Gs  = (unsigned*)(esm + 131072);
    float*    Hs  = (float*)(esm + 131072);
    unsigned* Ssm = (unsigned*)(esm + 200704);
    float*    Qsm = (float*)(esm + 209408);
    float*    red = (float*)(esm + 218112);

    const int t = threadIdx.x;
    const int lane = t & 31, w = t >> 5;
    const int lm = lane >> 2, lk = lane & 3;

    // load combined Cheb matrices to smem (tf32, swizzled)
    for (int i = t; i < 16384; i += 256) {
        int d = i >> 7, c = i & 127;
        int sidx = d * 128 + (c ^ (8 * (d & 3)));
        Acs[sidx] = f2tf(__ldg(g_A + i));
        Bcs[sidx] = f2tf(__ldg(g_B + i));
    }
    __syncthreads();

    const int d = t & 127, half = t >> 7;
    const float ga = gamma_[d], be = beta_[d], al = alpha_[d];
    const float lw0 = linW[d], lw1 = linW[128 + d];
    const float lb = __ldg(linb);

    const int wy = w >> 1, wx = w & 1;
    const int m0 = wy * 32, n0 = wx * 64, nq0 = w * 16;
    const int nIter = (E + 15) >> 4;

    for (int it = blockIdx.x; it < nIter; it += gridDim.x) {
        const int ebase = it * 16;

        // ---- stage A: gather + GraphNorm, write g (tf32) + S closed form ----
#pragma unroll
        for (int j = 0; j < 8; j++) {
            int el = half * 8 + j;
            int e = ebase + el;
            if (e < E) {
                float xv[8];
#pragma unroll
                for (int i = 0; i < 8; i++) {
                    int node = __ldg(&members[e * 8 + i]);
                    xv[i] = g_x[(size_t)node * 128 + d];
                }
                float mean = 0.0f;
#pragma unroll
                for (int i = 0; i < 8; i++) mean += xv[i];
                mean *= 0.125f;
                float am = al * mean;
                float var = 0.0f, ct[8];
#pragma unroll
                for (int i = 0; i < 8; i++) { ct[i] = xv[i] - am; var += ct[i] * ct[i]; }
                float inv = ga * rsqrtf(var * 0.125f + EPSF);
#pragma unroll
                for (int i = 0; i < 8; i++)
                    Gs[(el * 8 + i) * 132 + d] = f2tf(ct[i] * inv + be);
                float S = inv * 8.0f * mean * (1.0f - al) + 8.0f * be;
                Ssm[el * 132 + d] = f2tf(S);
            } else {
#pragma unroll
                for (int i = 0; i < 8; i++) Gs[(el * 8 + i) * 132 + d] = 0u;
                Ssm[el * 132 + d] = 0u;
            }
        }
        __syncthreads();

        // ---- stage B: MMAs. main: g[128,128]@A[128,128]; q: S[16,128]@B ----
        float acc[2][8][4];
        float qac[2][4];
#pragma unroll
        for (int mf = 0; mf < 2; mf++)
#pragma unroll
            for (int nf = 0; nf < 8; nf++)
#pragma unroll
                for (int r = 0; r < 4; r++) acc[mf][nf][r] = 0.0f;
#pragma unroll
        for (int nf = 0; nf < 2; nf++)
#pragma unroll
            for (int r = 0; r < 4; r++) qac[nf][r] = 0.0f;

#pragma unroll
        for (int ks = 0; ks < 16; ks++) {
            const int k0 = ks * 8;
            const int sw = 8 * lk;
            unsigned a[2][4];
#pragma unroll
            for (int mf = 0; mf < 2; mf++) {
                int rb = m0 + mf * 16;
                a[mf][0] = Gs[(rb + lm) * 132 + k0 + lk];
                a[mf][1] = Gs[(rb + lm + 8) * 132 + k0 + lk];
                a[mf][2] = Gs[(rb + lm) * 132 + k0 + lk + 4];
                a[mf][3] = Gs[(rb + lm + 8) * 132 + k0 + lk + 4];
            }
            unsigned b[8][2];
#pragma unroll
            for (int nf = 0; nf < 8; nf++) {
                int cb = n0 + nf * 8;
                b[nf][0] = Acs[(k0 + lk) * 128 + ((cb + lm) ^ sw)];
                b[nf][1] = Acs[(k0 + lk + 4) * 128 + ((cb + lm) ^ sw)];
            }
#pragma unroll
            for (int mf = 0; mf < 2; mf++)
#pragma unroll
                for (int nf = 0; nf < 8; nf++)
                    mma8(acc[mf][nf], a[mf][0], a[mf][1], a[mf][2], a[mf][3],
                         b[nf][0], b[nf][1]);
            // q MMA (warp-private n16 slice)
            unsigned sa0 = Ssm[lm * 132 + k0 + lk];
            unsigned sa1 = Ssm[(lm + 8) * 132 + k0 + lk];
            unsigned sa2 = Ssm[lm * 132 + k0 + lk + 4];
            unsigned sa3 = Ssm[(lm + 8) * 132 + k0 + lk + 4];
#pragma unroll
            for (int nf = 0; nf < 2; nf++) {
                int cb = nq0 + nf * 8;
                unsigned qb0 = Bcs[(k0 + lk) * 128 + ((cb + lm) ^ sw)];
                unsigned qb1 = Bcs[(k0 + lk + 4) * 128 + ((cb + lm) ^ sw)];
                mma8(qac[nf], sa0, sa1, sa2, sa3, qb0, qb1);
            }
        }
        // write Qsm (+chebb folded in)
#pragma unroll
        for (int nf = 0; nf < 2; nf++) {
            int c = nq0 + nf * 8 + 2 * lk;
            float cb0 = __ldg(chebb + c), cb1 = __ldg(chebb + c + 1);
            Qsm[lm * 136 + c]           = qac[nf][0] + cb0;
            Qsm[lm * 136 + c + 1]       = qac[nf][1] + cb1;
            Qsm[(lm + 8) * 136 + c]     = qac[nf][2] + cb0;
            Qsm[(lm + 8) * 136 + c + 1] = qac[nf][3] + cb1;
        }
        __syncthreads();

        // ---- stage C: h = clip(acc + Q[e][c]) -> Hs (reuses Gs space) ----
#pragma unroll
        for (int mf = 0; mf < 2; mf++) {
            int rb = m0 + mf * 16 + lm;
            int e0 = rb >> 3;
            int e1 = (rb + 8) >> 3;
#pragma unroll
            for (int nf = 0; nf < 8; nf++) {
                int c = n0 + nf * 8 + 2 * lk;
                float q00 = Qsm[e0 * 136 + c], q01 = Qsm[e0 * 136 + c + 1];
                float q10 = Qsm[e1 * 136 + c], q11 = Qsm[e1 * 136 + c + 1];
                float2 v0, v1;
                v0.x = clipf(acc[mf][nf][0] + q00);
                v0.y = clipf(acc[mf][nf][1] + q01);
                v1.x = clipf(acc[mf][nf][2] + q10);
                v1.y = clipf(acc[mf][nf][3] + q11);
                *(float2*)&Hs[rb * 136 + c]       = v0;
                *(float2*)&Hs[(rb + 8) * 136 + c] = v1;
            }
        }
        __syncthreads();

        // ---- stage D: pooling + linear head + sigmoid ----
        float contrib[8];
#pragma unroll
        for (int j = 0; j < 8; j++) {
            int el = half * 8 + j;
            float mx = -2.0f, mn = 2.0f, ss = 0.0f;
#pragma unroll
            for (int i = 0; i < 8; i++) {
                float h = Hs[(el * 8 + i) * 136 + d];
                mx = fmaxf(mx, h);
                mn = fminf(mn, h);
                ss += h * h;
            }
            contrib[j] = (mx - mn) * lw0 + sqrtf(ss * 0.125f) * lw1;
        }
#pragma unroll
        for (int j = 0; j < 8; j++) {
            float v = contrib[j];
            v += __shfl_xor_sync(0xffffffffu, v, 16);
            v += __shfl_xor_sync(0xffffffffu, v, 8);
            v += __shfl_xor_sync(0xffffffffu, v, 4);
            v += __shfl_xor_sync(0xffffffffu, v, 2);
            v += __shfl_xor_sync(0xffffffffu, v, 1);
            if (lane == 0) red[(half * 8 + j) * 4 + (w & 3)] = v;
        }
        __syncthreads();
        if (t < 16) {
            int e = ebase + t;
            if (e < E) {
                float* r = red + t * 4;
                float logit = r[0] + r[1] + r[2] + r[3] + lb;
                out[e] = 1.0f / (1.0f + expf(-logit));
            }
        }
        __syncthreads();   // protect Gs/Hs/Qsm/red before next iteration
    }
}

// ---------------------------------------------------------------------------
extern "C" void kernel_launch(void* const* d_in, const int* in_sizes, int n_in,
                              void* d_out, int out_size) {
    const float* pos   = (const float*)d_in[0];
    const float* Wenc  = (const float*)d_in[1];
    const float* benc  = (const float*)d_in[2];
    const float* gam   = (const float*)d_in[3];
    const float* bet   = (const float*)d_in[4];
    const float* alp   = (const float*)d_in[5];
    const float* chebW = (const float*)d_in[6];
    const float* chebb = (const float*)d_in[7];
    const float* linW  = (const float*)d_in[8];
    const float* linb  = (const float*)d_in[9];
    const int*   membs = (const int*)d_in[10];

    int N = in_sizes[0] / FDIM;   // 50000
    int E = in_sizes[10] / 8;     // 20000

    prep_kernel<<<(DDIM * DDIM + 255) / 256, 256>>>(chebW);
    encoder_mma<<<(N + 127) / 128, 256>>>(pos, Wenc, benc, N);

    cudaFuncSetAttribute(edge_mma, cudaFuncAttributeMaxDynamicSharedMemorySize,
                         ESMEM);
    int nIter = (E + 15) / 16;
    int grid = nIter < 148 ? nIter : 148;
    edge_mma<<<grid, 256, ESMEM>>>(membs, gam, bet, alp, chebb, linW, linb,
                                   (float*)d_out, E);
}

// round 4
// speedup vs baseline: 3.4823x; 1.2027x over previous
#include <cuda_runtime.h>
#include <math.h>
#include <stdint.h>

#define FDIM 512
#define DDIM 128
#define NMAX 50048
#define EPSF 1e-5f

// Scratch (allocation-free rule: device globals)
__device__ float g_x[(size_t)NMAX * DDIM];      // encoded node features
__device__ unsigned g_Au[DDIM * DDIM];          // Cheb A, tf32, swizzled
__device__ unsigned g_Bu[DDIM * DDIM];          // Cheb B, tf32, swizzled

__device__ __forceinline__ unsigned f2tf(float x) {
    unsigned r; asm("cvt.rna.tf32.f32 %0, %1;" : "=r"(r) : "f"(x)); return r;
}
__device__ __forceinline__ void mma8(float* c, unsigned a0, unsigned a1,
                                     unsigned a2, unsigned a3,
                                     unsigned b0, unsigned b1) {
    asm volatile(
        "mma.sync.aligned.m16n8k8.row.col.f32.tf32.tf32.f32 "
        "{%0,%1,%2,%3},{%4,%5,%6,%7},{%8,%9},{%0,%1,%2,%3};"
        : "+f"(c[0]), "+f"(c[1]), "+f"(c[2]), "+f"(c[3])
        : "r"(a0), "r"(a1), "r"(a2), "r"(a3), "r"(b0), "r"(b1));
}
__device__ __forceinline__ float clipf(float v) {
    return fminf(1.0f, fmaxf(-1.0f, v));
}

// ---------------------------------------------------------------------------
// Kernel 1: combine Cheb weights (closed form of K=3 Cheb on 8-clique),
// emit tf32 + swizzled layout ready for MMA fragment loads:
//   sidx = d*128 + (c ^ (8*(d&3)))
// ---------------------------------------------------------------------------
__global__ void prep_kernel(const float* __restrict__ chebW) {
    int idx = blockIdx.x * blockDim.x + threadIdx.x;
    if (idx < DDIM * DDIM) {
        int d = idx >> 7, c = idx & 127;
        float w0 = chebW[idx];
        float w1 = chebW[DDIM * DDIM + idx];
        float w2 = chebW[2 * DDIM * DDIM + idx];
        float a = w0 + w1 * (1.0f / 7.0f) - w2 * (47.0f / 49.0f);
        float b = -w1 * (1.0f / 7.0f) + w2 * (12.0f / 49.0f);
        int sidx = d * 128 + (c ^ (8 * (d & 3)));
        g_Au[sidx] = f2tf(a);
        g_Bu[sidx] = f2tf(b);
    }
}

// ---------------------------------------------------------------------------
// Kernel 2: encoder  x = clip(pos @ W_enc + b, -1, 1) via tf32 mma.sync.
// (unchanged from R2 — known good)
// ---------------------------------------------------------------------------
__global__ __launch_bounds__(256, 2)
void encoder_mma(const float* __restrict__ pos, const float* __restrict__ W,
                 const float* __restrict__ bias, int N) {
    __shared__ unsigned As[2][128 * 20];
    __shared__ unsigned Bs[2][16 * 128];

    const int t = threadIdx.x;
    const int m0 = blockIdx.x * 128;
    const int lane = t & 31, w = t >> 5;
    const int wy = w >> 1, wx = w & 1;
    const int lm = lane >> 2, lk = lane & 3;

    const int am = t >> 1, aq = t & 1;
    const bool aok = (m0 + am) < N;
    const float* ap = pos + (size_t)(m0 + am) * FDIM + aq * 8;
    const int bk = t >> 4, bq = t & 15;

    float acc[2][8][4];
#pragma unroll
    for (int mf = 0; mf < 2; mf++)
#pragma unroll
        for (int nf = 0; nf < 8; nf++)
#pragma unroll
            for (int r = 0; r < 4; r++) acc[mf][nf][r] = 0.0f;

    float4 pa0, pa1, pb0, pb1;
    if (aok) { pa0 = *(const float4*)(ap); pa1 = *(const float4*)(ap + 4); }
    else     { pa0 = make_float4(0,0,0,0); pa1 = make_float4(0,0,0,0); }
    {
        const float* bp = W + bk * 128 + bq * 8;
        pb0 = *(const float4*)(bp);
        pb1 = *(const float4*)(bp + 4);
    }
    {
        uint4 ua0 = make_uint4(f2tf(pa0.x), f2tf(pa0.y), f2tf(pa0.z), f2tf(pa0.w));
        uint4 ua1 = make_uint4(f2tf(pa1.x), f2tf(pa1.y), f2tf(pa1.z), f2tf(pa1.w));
        *(uint4*)&As[0][am * 20 + aq * 8]     = ua0;
        *(uint4*)&As[0][am * 20 + aq * 8 + 4] = ua1;
        int n = (bq * 8) ^ (8 * (bk & 3));
        uint4 ub0 = make_uint4(f2tf(pb0.x), f2tf(pb0.y), f2tf(pb0.z), f2tf(pb0.w));
        uint4 ub1 = make_uint4(f2tf(pb1.x), f2tf(pb1.y), f2tf(pb1.z), f2tf(pb1.w));
        *(uint4*)&Bs[0][bk * 128 + n]     = ub0;
        *(uint4*)&Bs[0][bk * 128 + n + 4] = ub1;
    }
    __syncthreads();

    for (int kt = 0; kt < 32; kt++) {
        const int s = kt & 1;
        if (kt < 31) {
            const float* a2p = ap + (kt + 1) * 16;
            if (aok) { pa0 = *(const float4*)(a2p); pa1 = *(const float4*)(a2p + 4); }
            else     { pa0 = make_float4(0,0,0,0);  pa1 = make_float4(0,0,0,0); }
            const float* bp = W + ((kt + 1) * 16 + bk) * 128 + bq * 8;
            pb0 = *(const float4*)(bp);
            pb1 = *(const float4*)(bp + 4);
        }
#pragma unroll
        for (int kh = 0; kh < 2; kh++) {
            const int k0 = kh * 8;
            unsigned a[2][4], b[8][2];
#pragma unroll
            for (int mf = 0; mf < 2; mf++) {
                int rb = wy * 32 + mf * 16;
                a[mf][0] = As[s][(rb + lm) * 20 + k0 + lk];
                a[mf][1] = As[s][(rb + lm + 8) * 20 + k0 + lk];
                a[mf][2] = As[s][(rb + lm) * 20 + k0 + lk + 4];
                a[mf][3] = As[s][(rb + lm + 8) * 20 + k0 + lk + 4];
            }
#pragma unroll
            for (int nf = 0; nf < 8; nf++) {
                int cb = wx * 64 + nf * 8;
                b[nf][0] = Bs[s][(k0 + lk) * 128 + ((cb + lm) ^ (8 * lk))];
                b[nf][1] = Bs[s][(k0 + lk + 4) * 128 + ((cb + lm) ^ (8 * lk))];
            }
#pragma unroll
            for (int mf = 0; mf < 2; mf++)
#pragma unroll
                for (int nf = 0; nf < 8; nf++)
                    mma8(acc[mf][nf], a[mf][0], a[mf][1], a[mf][2], a[mf][3],
                         b[nf][0], b[nf][1]);
        }
        if (kt < 31) {
            const int s2 = s ^ 1;
            uint4 ua0 = make_uint4(f2tf(pa0.x), f2tf(pa0.y), f2tf(pa0.z), f2tf(pa0.w));
            uint4 ua1 = make_uint4(f2tf(pa1.x), f2tf(pa1.y), f2tf(pa1.z), f2tf(pa1.w));
            *(uint4*)&As[s2][am * 20 + aq * 8]     = ua0;
            *(uint4*)&As[s2][am * 20 + aq * 8 + 4] = ua1;
            int n = (bq * 8) ^ (8 * (bk & 3));
            uint4 ub0 = make_uint4(f2tf(pb0.x), f2tf(pb0.y), f2tf(pb0.z), f2tf(pb0.w));
            uint4 ub1 = make_uint4(f2tf(pb1.x), f2tf(pb1.y), f2tf(pb1.z), f2tf(pb1.w));
            *(uint4*)&Bs[s2][bk * 128 + n]     = ub0;
            *(uint4*)&Bs[s2][bk * 128 + n + 4] = ub1;
            __syncthreads();
        }
    }

#pragma unroll
    for (int mf = 0; mf < 2; mf++) {
        int r0 = m0 + wy * 32 + mf * 16 + lm;
#pragma unroll
        for (int nf = 0; nf < 8; nf++) {
            int c = wx * 64 + nf * 8 + 2 * lk;
            float b0 = __ldg(bias + c), b1 = __ldg(bias + c + 1);
            if (r0 < N) {
                float2 v;
                v.x = clipf(acc[mf][nf][0] + b0);
                v.y = clipf(acc[mf][nf][1] + b1);
                *(float2*)&g_x[(size_t)r0 * 128 + c] = v;
            }
            if (r0 + 8 < N) {
                float2 v;
                v.x = clipf(acc[mf][nf][2] + b0);
                v.y = clipf(acc[mf][nf][3] + b1);
                *(float2*)&g_x[(size_t)(r0 + 8) * 128 + c] = v;
            }
        }
    }
}

// ---------------------------------------------------------------------------
// Kernel 3: fused per-hyperedge pipeline, 16 edges/iter, tf32 mma.sync.
// R4: vectorized gather (float4, 4ch x 2edges per thread), member indices
// staged in smem, A/B copied pre-swizzled, LDS.64 Q-loads.
// smem layout (dynamic, 218368+512+64 B):
//   Acs  unsigned[16384]  @0       : Cheb A (pre-swizzled tf32)
//   Bcs  unsigned[16384]  @65536   : Cheb B
//   Gs   unsigned[128*132]@131072  : g row-major [row][d], stride 132
//   Hs   float  [128*136] @131072  : (union w/ Gs) h row-major, stride 136
//   Ssm  unsigned[16*132] @200704  : S row-major [e][d], stride 132
//   Qsm  float  [16*136]  @209408  : q = S@B + chebb
//   red  float  [16*4]    @218112
//   msm  int    [128]     @218368
// ---------------------------------------------------------------------------
#define ESMEM (218368 + 512)

__global__ __launch_bounds__(256, 1)
void edge_mma(const int* __restrict__ members,
              const float* __restrict__ gamma_, const float* __restrict__ beta_,
              const float* __restrict__ alpha_, const float* __restrict__ chebb,
              const float* __restrict__ linW, const float* __restrict__ linb,
              float* __restrict__ out, int E) {
    extern __shared__ unsigned char esm[];
    unsigned* Acs = (unsigned*)esm;
    unsigned* Bcs = (unsigned*)(esm + 65536);
    unsigned* Gs  = (unsigned*)(esm + 131072);
    float*    Hs  = (float*)(esm + 131072);
    unsigned* Ssm = (unsigned*)(esm + 200704);
    float*    Qsm = (float*)(esm + 209408);
    float*    red = (float*)(esm + 218112);
    int*      msm = (int*)(esm + 218368);

    const int t = threadIdx.x;
    const int lane = t & 31, w = t >> 5;
    const int lm = lane >> 2, lk = lane & 3;

    // copy pre-swizzled tf32 Cheb matrices (pure uint4 copy)
    {
        const uint4* Ag = (const uint4*)g_Au;
        const uint4* Bg = (const uint4*)g_Bu;
        uint4* Al = (uint4*)Acs;
        uint4* Bl = (uint4*)Bcs;
        for (int i = t; i < 4096; i += 256) {
            Al[i] = __ldg(Ag + i);
            Bl[i] = __ldg(Bg + i);
        }
    }

    // gather mapping: c4 = channel group (4 ch), ep -> edges 2ep, 2ep+1
    const int c4 = t & 31, ep = t >> 5;
    const float4 ga4 = *(const float4*)(gamma_ + 4 * c4);
    const float4 be4 = *(const float4*)(beta_  + 4 * c4);
    const float4 al4 = *(const float4*)(alpha_ + 4 * c4);

    // stage D mapping: per-channel params
    const int d = t & 127, half = t >> 7;
    const float lw0 = linW[d], lw1 = linW[128 + d];
    const float lb = __ldg(linb);

    const int wy = w >> 1, wx = w & 1;
    const int m0 = wy * 32, n0 = wx * 64, nq0 = w * 16;
    const int nIter = (E + 15) >> 4;

    __syncthreads();   // Acs/Bcs ready

    for (int it = blockIdx.x; it < nIter; it += gridDim.x) {
        const int ebase = it * 16;

        // stage members for this iteration
        if (t < 128) msm[t] = __ldg(&members[ebase * 8 + t]);
        __syncthreads();

        // ---- stage A: gather + GraphNorm (4 channels x 2 edges / thread) ----
#pragma unroll
        for (int ee = 0; ee < 2; ee++) {
            const int el = 2 * ep + ee;
            const int e = ebase + el;
            unsigned* grow = Gs + el * 8 * 132 + 4 * c4;
            unsigned* srow = Ssm + el * 132 + 4 * c4;
            if (e < E) {
                float4 xv[8];
#pragma unroll
                for (int i = 0; i < 8; i++) {
                    int node = msm[el * 8 + i];
                    xv[i] = *(const float4*)(g_x + (size_t)node * 128 + 4 * c4);
                }
                float4 mean = make_float4(0, 0, 0, 0);
#pragma unroll
                for (int i = 0; i < 8; i++) {
                    mean.x += xv[i].x; mean.y += xv[i].y;
                    mean.z += xv[i].z; mean.w += xv[i].w;
                }
                mean.x *= 0.125f; mean.y *= 0.125f;
                mean.z *= 0.125f; mean.w *= 0.125f;
                float4 am = make_float4(al4.x * mean.x, al4.y * mean.y,
                                        al4.z * mean.z, al4.w * mean.w);
                float4 var = make_float4(0, 0, 0, 0);
#pragma unroll
                for (int i = 0; i < 8; i++) {
                    xv[i].x -= am.x; xv[i].y -= am.y;
                    xv[i].z -= am.z; xv[i].w -= am.w;
                    var.x += xv[i].x * xv[i].x; var.y += xv[i].y * xv[i].y;
                    var.z += xv[i].z * xv[i].z; var.w += xv[i].w * xv[i].w;
                }
                float4 inv;
                inv.x = ga4.x * rsqrtf(var.x * 0.125f + EPSF);
                inv.y = ga4.y * rsqrtf(var.y * 0.125f + EPSF);
                inv.z = ga4.z * rsqrtf(var.z * 0.125f + EPSF);
                inv.w = ga4.w * rsqrtf(var.w * 0.125f + EPSF);
#pragma unroll
                for (int i = 0; i < 8; i++) {
                    uint4 u;
                    u.x = f2tf(xv[i].x * inv.x + be4.x);
                    u.y = f2tf(xv[i].y * inv.y + be4.y);
                    u.z = f2tf(xv[i].z * inv.z + be4.z);
                    u.w = f2tf(xv[i].w * inv.w + be4.w);
                    *(uint4*)(grow + i * 132) = u;
                }
                uint4 su;
                su.x = f2tf(inv.x * 8.0f * mean.x * (1.0f - al4.x) + 8.0f * be4.x);
                su.y = f2tf(inv.y * 8.0f * mean.y * (1.0f - al4.y) + 8.0f * be4.y);
                su.z = f2tf(inv.z * 8.0f * mean.z * (1.0f - al4.z) + 8.0f * be4.z);
                su.w = f2tf(inv.w * 8.0f * mean.w * (1.0f - al4.w) + 8.0f * be4.w);
                *(uint4*)srow = su;
            } else {
                uint4 z = make_uint4(0, 0, 0, 0);
#pragma unroll
                for (int i = 0; i < 8; i++) *(uint4*)(grow + i * 132) = z;
                *(uint4*)srow = z;
            }
        }
        __syncthreads();

        // ---- stage B: MMAs. main: g[128,128]@A ; q: S[16,128]@B ----
        float acc[2][8][4];
        float qac[2][4];
#pragma unroll
        for (int mf = 0; mf < 2; mf++)
#pragma unroll
            for (int nf = 0; nf < 8; nf++)
#pragma unroll
                for (int r = 0; r < 4; r++) acc[mf][nf][r] = 0.0f;
#pragma unroll
        for (int nf = 0; nf < 2; nf++)
#pragma unroll
            for (int r = 0; r < 4; r++) qac[nf][r] = 0.0f;

#pragma unroll
        for (int ks = 0; ks < 16; ks++) {
            const int k0 = ks * 8;
            const int sw = 8 * lk;
            unsigned a[2][4];
#pragma unroll
            for (int mf = 0; mf < 2; mf++) {
                int rb = m0 + mf * 16;
                a[mf][0] = Gs[(rb + lm) * 132 + k0 + lk];
                a[mf][1] = Gs[(rb + lm + 8) * 132 + k0 + lk];
                a[mf][2] = Gs[(rb + lm) * 132 + k0 + lk + 4];
                a[mf][3] = Gs[(rb + lm + 8) * 132 + k0 + lk + 4];
            }
            unsigned b[8][2];
#pragma unroll
            for (int nf = 0; nf < 8; nf++) {
                int cb = n0 + nf * 8;
                b[nf][0] = Acs[(k0 + lk) * 128 + ((cb + lm) ^ sw)];
                b[nf][1] = Acs[(k0 + lk + 4) * 128 + ((cb + lm) ^ sw)];
            }
#pragma unroll
            for (int mf = 0; mf < 2; mf++)
#pragma unroll
                for (int nf = 0; nf < 8; nf++)
                    mma8(acc[mf][nf], a[mf][0], a[mf][1], a[mf][2], a[mf][3],
                         b[nf][0], b[nf][1]);
            unsigned sa0 = Ssm[lm * 132 + k0 + lk];
            unsigned sa1 = Ssm[(lm + 8) * 132 + k0 + lk];
            unsigned sa2 = Ssm[lm * 132 + k0 + lk + 4];
            unsigned sa3 = Ssm[(lm + 8) * 132 + k0 + lk + 4];
#pragma unroll
            for (int nf = 0; nf < 2; nf++) {
                int cb = nq0 + nf * 8;
                unsigned qb0 = Bcs[(k0 + lk) * 128 + ((cb + lm) ^ sw)];
                unsigned qb1 = Bcs[(k0 + lk + 4) * 128 + ((cb + lm) ^ sw)];
                mma8(qac[nf], sa0, sa1, sa2, sa3, qb0, qb1);
            }
        }
        // write Qsm (+chebb folded in)
#pragma unroll
        for (int nf = 0; nf < 2; nf++) {
            int c = nq0 + nf * 8 + 2 * lk;
            float cb0 = __ldg(chebb + c), cb1 = __ldg(chebb + c + 1);
            Qsm[lm * 136 + c]           = qac[nf][0] + cb0;
            Qsm[lm * 136 + c + 1]       = qac[nf][1] + cb1;
            Qsm[(lm + 8) * 136 + c]     = qac[nf][2] + cb0;
            Qsm[(lm + 8) * 136 + c + 1] = qac[nf][3] + cb1;
        }
        __syncthreads();

        // ---- stage C: h = clip(acc + Q[e][c]) -> Hs ----
#pragma unroll
        for (int mf = 0; mf < 2; mf++) {
            int rb = m0 + mf * 16 + lm;
            int e0 = rb >> 3;
            int e1 = (rb + 8) >> 3;
#pragma unroll
            for (int nf = 0; nf < 8; nf++) {
                int c = n0 + nf * 8 + 2 * lk;
                float2 q0 = *(const float2*)&Qsm[e0 * 136 + c];
                float2 q1 = *(const float2*)&Qsm[e1 * 136 + c];
                float2 v0, v1;
                v0.x = clipf(acc[mf][nf][0] + q0.x);
                v0.y = clipf(acc[mf][nf][1] + q0.y);
                v1.x = clipf(acc[mf][nf][2] + q1.x);
                v1.y = clipf(acc[mf][nf][3] + q1.y);
                *(float2*)&Hs[rb * 136 + c]       = v0;
                *(float2*)&Hs[(rb + 8) * 136 + c] = v1;
            }
        }
        __syncthreads();

        // ---- stage D: pooling + linear head + sigmoid ----
        float contrib[8];
#pragma unroll
        for (int j = 0; j < 8; j++) {
            int el = half * 8 + j;
            float mx = -2.0f, mn = 2.0f, ss = 0.0f;
#pragma unroll
            for (int i = 0; i < 8; i++) {
                float h = Hs[(el * 8 + i) * 136 + d];
                mx = fmaxf(mx, h);
                mn = fminf(mn, h);
                ss += h * h;
            }
            contrib[j] = (mx - mn) * lw0 + sqrtf(ss * 0.125f) * lw1;
        }
#pragma unroll
        for (int j = 0; j < 8; j++) {
            float v = contrib[j];
            v += __shfl_xor_sync(0xffffffffu, v, 16);
            v += __shfl_xor_sync(0xffffffffu, v, 8);
            v += __shfl_xor_sync(0xffffffffu, v, 4);
            v += __shfl_xor_sync(0xffffffffu, v, 2);
            v += __shfl_xor_sync(0xffffffffu, v, 1);
            if (lane == 0) red[(half * 8 + j) * 4 + (w & 3)] = v;
        }
        __syncthreads();
        if (t < 16) {
            int e = ebase + t;
            if (e < E) {
                float* r = red + t * 4;
                float logit = r[0] + r[1] + r[2] + r[3] + lb;
                out[e] = 1.0f / (1.0f + expf(-logit));
            }
        }
        __syncthreads();   // protect smem before next iteration
    }
}

// ---------------------------------------------------------------------------
extern "C" void kernel_launch(void* const* d_in, const int* in_sizes, int n_in,
                              void* d_out, int out_size) {
    const float* pos   = (const float*)d_in[0];
    const float* Wenc  = (const float*)d_in[1];
    const float* benc  = (const float*)d_in[2];
    const float* gam   = (const float*)d_in[3];
    const float* bet   = (const float*)d_in[4];
    const float* alp   = (const float*)d_in[5];
    const float* chebW = (const float*)d_in[6];
    const float* chebb = (const float*)d_in[7];
    const float* linW  = (const float*)d_in[8];
    const float* linb  = (const float*)d_in[9];
    const int*   membs = (const int*)d_in[10];

    int N = in_sizes[0] / FDIM;   // 50000
    int E = in_sizes[10] / 8;     // 20000

    prep_kernel<<<(DDIM * DDIM + 255) / 256, 256>>>(chebW);
    encoder_mma<<<(N + 127) / 128, 256>>>(pos, Wenc, benc, N);

    cudaFuncSetAttribute(edge_mma, cudaFuncAttributeMaxDynamicSharedMemorySize,
                         ESMEM);
    int nIter = (E + 15) / 16;
    int grid = nIter < 148 ? nIter : 148;
    edge_mma<<<grid, 256, ESMEM>>>(membs, gam, bet, alp, chebb, linW, linb,
                                   (float*)d_out, E);
}

// round 5
// speedup vs baseline: 3.9810x; 1.1432x over previous
#include <cuda_runtime.h>
#include <math.h>
#include <stdint.h>

#define FDIM 512
#define DDIM 128
#define NMAX 50048
#define EPSF 1e-5f

// Scratch (allocation-free rule: device globals)
__device__ float g_x[(size_t)NMAX * DDIM];      // encoded node features

__device__ __forceinline__ unsigned f2tf(float x) {
    unsigned r; asm("cvt.rna.tf32.f32 %0, %1;" : "=r"(r) : "f"(x)); return r;
}
__device__ __forceinline__ void mma8(float* c, unsigned a0, unsigned a1,
                                     unsigned a2, unsigned a3,
                                     unsigned b0, unsigned b1) {
    asm volatile(
        "mma.sync.aligned.m16n8k8.row.col.f32.tf32.tf32.f32 "
        "{%0,%1,%2,%3},{%4,%5,%6,%7},{%8,%9},{%0,%1,%2,%3};"
        : "+f"(c[0]), "+f"(c[1]), "+f"(c[2]), "+f"(c[3])
        : "r"(a0), "r"(a1), "r"(a2), "r"(a3), "r"(b0), "r"(b1));
}
__device__ __forceinline__ float clipf(float v) {
    return fminf(1.0f, fmaxf(-1.0f, v));
}
__device__ __forceinline__ uint32_t smem_u32(const void* p) {
    uint32_t a;
    asm("{ .reg .u64 t; cvta.to.shared.u64 t, %1; cvt.u32.u64 %0, t; }"
        : "=r"(a) : "l"(p));
    return a;
}
__device__ __forceinline__ void cpasync16(uint32_t dst, const void* src, int szr) {
    asm volatile("cp.async.ca.shared.global [%0], [%1], 16, %2;"
                 :: "r"(dst), "l"(src), "r"(szr) : "memory");
}
#define CP_COMMIT() asm volatile("cp.async.commit_group;" ::: "memory")
#define CP_WAIT1()  asm volatile("cp.async.wait_group 1;" ::: "memory")

// ---------------------------------------------------------------------------
// Kernel 1: encoder  x = clip(pos @ W_enc + b, -1, 1) via tf32 mma.sync.
// 3-stage cp.async pipeline, truncated tf32 (no cvt), 128x128 tile, BK=16,
// 8 warps (4x2), warp tile 32x64.
// A smem: [row][k] stride 20 words; B smem: [k][n] word-swizzle n^(8*(k&3)).
// ---------------------------------------------------------------------------
#define ENC_A_BYTES (128 * 20 * 4)                    // 10240
#define ENC_B_BYTES (16 * 128 * 4)                    // 8192
#define ENC_SMEM    (3 * (ENC_A_BYTES + ENC_B_BYTES)) // 55296

__global__ __launch_bounds__(256, 2)
void encoder_cp(const float* __restrict__ pos, const float* __restrict__ W,
                const float* __restrict__ bias, int N) {
    extern __shared__ unsigned char sm[];
    const uint32_t smb = smem_u32(sm);

    const int t = threadIdx.x, lane = t & 31, w = t >> 5;
    const int wy = w >> 1, wx = w & 1;
    const int lm = lane >> 2, lk = lane & 3;
    const int m0 = blockIdx.x * 128;

    // loader mapping
    const int ar0 = t >> 2, akq = t & 3;      // A: rows ar0, ar0+64; k-quads
    const int bk0 = t >> 5, bnq = t & 31;     // B: k-rows bk0, bk0+8; n-quads

    float acc[2][8][4];
#pragma unroll
    for (int mf = 0; mf < 2; mf++)
#pragma unroll
        for (int nf = 0; nf < 8; nf++)
#pragma unroll
            for (int r = 0; r < 4; r++) acc[mf][nf][r] = 0.0f;

    // issue one k16 tile into stage s
    auto issue = [&](int s, int kt) {
        const uint32_t abase = smb + s * ENC_A_BYTES;
        const uint32_t bbase = smb + 3 * ENC_A_BYTES + s * ENC_B_BYTES;
#pragma unroll
        for (int h = 0; h < 2; h++) {
            int r = ar0 + h * 64;
            const float* src = pos + (size_t)(m0 + r) * FDIM + kt * 16 + akq * 4;
            uint32_t dst = abase + (r * 20 + akq * 4) * 4;
            cpasync16(dst, src, (m0 + r) < N ? 16 : 0);
        }
#pragma unroll
        for (int h = 0; h < 2; h++) {
            int k = bk0 + h * 8;
            const float* src = W + (size_t)(kt * 16 + k) * 128 + bnq * 4;
            uint32_t dst = bbase + (k * 128 + ((bnq * 4) ^ (8 * (k & 3)))) * 4;
            cpasync16(dst, src, 16);
        }
    };

    issue(0, 0); CP_COMMIT();
    issue(1, 1); CP_COMMIT();

    for (int kt = 0; kt < 32; kt++) {
        const int s = kt % 3;
        CP_WAIT1();            // group kt complete
        __syncthreads();
        if (kt + 2 < 32) issue((kt + 2) % 3, kt + 2);
        CP_COMMIT();

        const unsigned* As = (const unsigned*)(sm + s * ENC_A_BYTES);
        const unsigned* Bs = (const unsigned*)(sm + 3 * ENC_A_BYTES + s * ENC_B_BYTES);
#pragma unroll
        for (int kh = 0; kh < 2; kh++) {
            const int k0 = kh * 8;
            unsigned a[2][4], b[8][2];
#pragma unroll
            for (int mf = 0; mf < 2; mf++) {
                int rb = wy * 32 + mf * 16;
                a[mf][0] = As[(rb + lm) * 20 + k0 + lk];
                a[mf][1] = As[(rb + lm + 8) * 20 + k0 + lk];
                a[mf][2] = As[(rb + lm) * 20 + k0 + lk + 4];
                a[mf][3] = As[(rb + lm + 8) * 20 + k0 + lk + 4];
            }
#pragma unroll
            for (int nf = 0; nf < 8; nf++) {
                int cb = wx * 64 + nf * 8;
                b[nf][0] = Bs[(k0 + lk) * 128 + ((cb + lm) ^ (8 * lk))];
                b[nf][1] = Bs[(k0 + lk + 4) * 128 + ((cb + lm) ^ (8 * lk))];
            }
#pragma unroll
            for (int mf = 0; mf < 2; mf++)
#pragma unroll
                for (int nf = 0; nf < 8; nf++)
                    mma8(acc[mf][nf], a[mf][0], a[mf][1], a[mf][2], a[mf][3],
                         b[nf][0], b[nf][1]);
        }
    }

    // epilogue: bias + hardtanh + store to g_x
#pragma unroll
    for (int mf = 0; mf < 2; mf++) {
        int r0 = m0 + wy * 32 + mf * 16 + lm;
#pragma unroll
        for (int nf = 0; nf < 8; nf++) {
            int c = wx * 64 + nf * 8 + 2 * lk;
            float b0 = __ldg(bias + c), b1 = __ldg(bias + c + 1);
            if (r0 < N) {
                float2 v;
                v.x = clipf(acc[mf][nf][0] + b0);
                v.y = clipf(acc[mf][nf][1] + b1);
                *(float2*)&g_x[(size_t)r0 * 128 + c] = v;
            }
            if (r0 + 8 < N) {
                float2 v;
                v.x = clipf(acc[mf][nf][2] + b0);
                v.y = clipf(acc[mf][nf][3] + b1);
                *(float2*)&g_x[(size_t)(r0 + 8) * 128 + c] = v;
            }
        }
    }
}

// ---------------------------------------------------------------------------
// Kernel 2: fused per-hyperedge pipeline, 16 edges/iter, tf32 mma.sync.
// R5: Cheb-combine (prep) folded in per-block; member indices via warp shfl.
// smem layout (dynamic, 218368 B):
//   Acs  unsigned[16384]  @0       : Cheb A (tf32, frag-swizzled)
//   Bcs  unsigned[16384]  @65536   : Cheb B
//   Gs   unsigned[128*132]@131072  : g row-major [row][d], stride 132
//   Hs   float  [128*136] @131072  : (union w/ Gs) h row-major, stride 136
//   Ssm  unsigned[16*132] @200704  : S row-major [e][d], stride 132
//   Qsm  float  [16*136]  @209408  : q = S@B + chebb
//   red  float  [16*4]    @218112
// ---------------------------------------------------------------------------
#define ESMEM 218368

__global__ __launch_bounds__(256, 1)
void edge_mma(const int* __restrict__ members, const float* __restrict__ chebW,
              const float* __restrict__ gamma_, const float* __restrict__ beta_,
              const float* __restrict__ alpha_, const float* __restrict__ chebb,
              const float* __restrict__ linW, const float* __restrict__ linb,
              float* __restrict__ out, int E) {
    extern __shared__ unsigned char esm[];
    unsigned* Acs = (unsigned*)esm;
    unsigned* Bcs = (unsigned*)(esm + 65536);
    unsigned* Gs  = (unsigned*)(esm + 131072);
    float*    Hs  = (float*)(esm + 131072);
    unsigned* Ssm = (unsigned*)(esm + 200704);
    float*    Qsm = (float*)(esm + 209408);
    float*    red = (float*)(esm + 218112);

    const int t = threadIdx.x;
    const int lane = t & 31, w = t >> 5;
    const int lm = lane >> 2, lk = lane & 3;

    // ---- fold of prep: A = W0 + W1/7 - 47/49 W2 ; B = -W1/7 + 12/49 W2 ----
    for (int i = t; i < 4096; i += 256) {
        int dd = i >> 5;
        int cg = (i & 31) * 4;
        const float* p0 = chebW + dd * 128 + cg;
        float4 w0 = __ldg((const float4*)(p0));
        float4 w1 = __ldg((const float4*)(p0 + 16384));
        float4 w2 = __ldg((const float4*)(p0 + 32768));
        int dst = dd * 128 + (cg ^ (8 * (dd & 3)));
        uint4 ua, ub;
        ua.x = f2tf(w0.x + w1.x * (1.0f/7.0f) - w2.x * (47.0f/49.0f));
        ua.y = f2tf(w0.y + w1.y * (1.0f/7.0f) - w2.y * (47.0f/49.0f));
        ua.z = f2tf(w0.z + w1.z * (1.0f/7.0f) - w2.z * (47.0f/49.0f));
        ua.w = f2tf(w0.w + w1.w * (1.0f/7.0f) - w2.w * (47.0f/49.0f));
        ub.x = f2tf(-w1.x * (1.0f/7.0f) + w2.x * (12.0f/49.0f));
        ub.y = f2tf(-w1.y * (1.0f/7.0f) + w2.y * (12.0f/49.0f));
        ub.z = f2tf(-w1.z * (1.0f/7.0f) + w2.z * (12.0f/49.0f));
        ub.w = f2tf(-w1.w * (1.0f/7.0f) + w2.w * (12.0f/49.0f));
        *(uint4*)&Acs[dst] = ua;
        *(uint4*)&Bcs[dst] = ub;
    }

    // gather mapping: c4 = channel group (4 ch), warp handles edges 2w, 2w+1
    const int c4 = t & 31;
    const float4 ga4 = *(const float4*)(gamma_ + 4 * c4);
    const float4 be4 = *(const float4*)(beta_  + 4 * c4);
    const float4 al4 = *(const float4*)(alpha_ + 4 * c4);

    // stage D mapping: per-channel params
    const int d = t & 127, half = t >> 7;
    const float lw0 = linW[d], lw1 = linW[128 + d];
    const float lb = __ldg(linb);

    const int wy = w >> 1, wx = w & 1;
    const int m0 = wy * 32, n0 = wx * 64, nq0 = w * 16;
    const int nIter = (E + 15) >> 4;

    __syncthreads();   // Acs/Bcs ready

    for (int it = blockIdx.x; it < nIter; it += gridDim.x) {
        const int ebase = it * 16;

        // per-warp member indices: lane<16 holds members of edges 2w, 2w+1
        int mreg = 0;
        {
            int e = ebase + 2 * w + (lane >> 3);
            if (lane < 16 && e < E)
                mreg = __ldg(&members[e * 8 + (lane & 7)]);
        }

        // ---- stage A: gather + GraphNorm (4 channels x 2 edges / thread) ----
#pragma unroll
        for (int ee = 0; ee < 2; ee++) {
            const int el = 2 * w + ee;
            const int e = ebase + el;
            unsigned* grow = Gs + el * 8 * 132 + 4 * c4;
            unsigned* srow = Ssm + el * 132 + 4 * c4;
            if (e < E) {
                float4 xv[8];
#pragma unroll
                for (int i = 0; i < 8; i++) {
                    int node = __shfl_sync(0xffffffffu, mreg, ee * 8 + i);
                    xv[i] = *(const float4*)(g_x + (size_t)node * 128 + 4 * c4);
                }
                float4 mean = make_float4(0, 0, 0, 0);
#pragma unroll
                for (int i = 0; i < 8; i++) {
                    mean.x += xv[i].x; mean.y += xv[i].y;
                    mean.z += xv[i].z; mean.w += xv[i].w;
                }
                mean.x *= 0.125f; mean.y *= 0.125f;
                mean.z *= 0.125f; mean.w *= 0.125f;
                float4 am = make_float4(al4.x * mean.x, al4.y * mean.y,
                                        al4.z * mean.z, al4.w * mean.w);
                float4 var = make_float4(0, 0, 0, 0);
#pragma unroll
                for (int i = 0; i < 8; i++) {
                    xv[i].x -= am.x; xv[i].y -= am.y;
                    xv[i].z -= am.z; xv[i].w -= am.w;
                    var.x += xv[i].x * xv[i].x; var.y += xv[i].y * xv[i].y;
                    var.z += xv[i].z * xv[i].z; var.w += xv[i].w * xv[i].w;
                }
                float4 inv;
                inv.x = ga4.x * rsqrtf(var.x * 0.125f + EPSF);
                inv.y = ga4.y * rsqrtf(var.y * 0.125f + EPSF);
                inv.z = ga4.z * rsqrtf(var.z * 0.125f + EPSF);
                inv.w = ga4.w * rsqrtf(var.w * 0.125f + EPSF);
#pragma unroll
                for (int i = 0; i < 8; i++) {
                    uint4 u;
                    u.x = f2tf(xv[i].x * inv.x + be4.x);
                    u.y = f2tf(xv[i].y * inv.y + be4.y);
                    u.z = f2tf(xv[i].z * inv.z + be4.z);
                    u.w = f2tf(xv[i].w * inv.w + be4.w);
                    *(uint4*)(grow + i * 132) = u;
                }
                uint4 su;
                su.x = f2tf(inv.x * 8.0f * mean.x * (1.0f - al4.x) + 8.0f * be4.x);
                su.y = f2tf(inv.y * 8.0f * mean.y * (1.0f - al4.y) + 8.0f * be4.y);
                su.z = f2tf(inv.z * 8.0f * mean.z * (1.0f - al4.z) + 8.0f * be4.z);
                su.w = f2tf(inv.w * 8.0f * mean.w * (1.0f - al4.w) + 8.0f * be4.w);
                *(uint4*)srow = su;
            } else {
                uint4 z = make_uint4(0, 0, 0, 0);
#pragma unroll
                for (int i = 0; i < 8; i++) *(uint4*)(grow + i * 132) = z;
                *(uint4*)srow = z;
            }
        }
        __syncthreads();

        // ---- stage B: MMAs. main: g[128,128]@A ; q: S[16,128]@B ----
        float acc[2][8][4];
        float qac[2][4];
#pragma unroll
        for (int mf = 0; mf < 2; mf++)
#pragma unroll
            for (int nf = 0; nf < 8; nf++)
#pragma unroll
                for (int r = 0; r < 4; r++) acc[mf][nf][r] = 0.0f;
#pragma unroll
        for (int nf = 0; nf < 2; nf++)
#pragma unroll
            for (int r = 0; r < 4; r++) qac[nf][r] = 0.0f;

#pragma unroll
        for (int ks = 0; ks < 16; ks++) {
            const int k0 = ks * 8;
            const int sw = 8 * lk;
            unsigned a[2][4];
#pragma unroll
            for (int mf = 0; mf < 2; mf++) {
                int rb = m0 + mf * 16;
                a[mf][0] = Gs[(rb + lm) * 132 + k0 + lk];
                a[mf][1] = Gs[(rb + lm + 8) * 132 + k0 + lk];
                a[mf][2] = Gs[(rb + lm) * 132 + k0 + lk + 4];
                a[mf][3] = Gs[(rb + lm + 8) * 132 + k0 + lk + 4];
            }
            unsigned b[8][2];
#pragma unroll
            for (int nf = 0; nf < 8; nf++) {
                int cb = n0 + nf * 8;
                b[nf][0] = Acs[(k0 + lk) * 128 + ((cb + lm) ^ sw)];
                b[nf][1] = Acs[(k0 + lk + 4) * 128 + ((cb + lm) ^ sw)];
            }
#pragma unroll
            for (int mf = 0; mf < 2; mf++)
#pragma unroll
                for (int nf = 0; nf < 8; nf++)
                    mma8(acc[mf][nf], a[mf][0], a[mf][1], a[mf][2], a[mf][3],
                         b[nf][0], b[nf][1]);
            unsigned sa0 = Ssm[lm * 132 + k0 + lk];
            unsigned sa1 = Ssm[(lm + 8) * 132 + k0 + lk];
            unsigned sa2 = Ssm[lm * 132 + k0 + lk + 4];
            unsigned sa3 = Ssm[(lm + 8) * 132 + k0 + lk + 4];
#pragma unroll
            for (int nf = 0; nf < 2; nf++) {
                int cb = nq0 + nf * 8;
                unsigned qb0 = Bcs[(k0 + lk) * 128 + ((cb + lm) ^ sw)];
                unsigned qb1 = Bcs[(k0 + lk + 4) * 128 + ((cb + lm) ^ sw)];
                mma8(qac[nf], sa0, sa1, sa2, sa3, qb0, qb1);
            }
        }
        // write Qsm (+chebb folded in)
#pragma unroll
        for (int nf = 0; nf < 2; nf++) {
            int c = nq0 + nf * 8 + 2 * lk;
            float cb0 = __ldg(chebb + c), cb1 = __ldg(chebb + c + 1);
            Qsm[lm * 136 + c]           = qac[nf][0] + cb0;
            Qsm[lm * 136 + c + 1]       = qac[nf][1] + cb1;
            Qsm[(lm + 8) * 136 + c]     = qac[nf][2] + cb0;
            Qsm[(lm + 8) * 136 + c + 1] = qac[nf][3] + cb1;
        }
        __syncthreads();

        // ---- stage C: h = clip(acc + Q[e][c]) -> Hs (reuses Gs space) ----
#pragma unroll
        for (int mf = 0; mf < 2; mf++) {
            int rb = m0 + mf * 16 + lm;
            int e0 = rb >> 3;
            int e1 = (rb + 8) >> 3;
#pragma unroll
            for (int nf = 0; nf < 8; nf++) {
                int c = n0 + nf * 8 + 2 * lk;
                float2 q0 = *(const float2*)&Qsm[e0 * 136 + c];
                float2 q1 = *(const float2*)&Qsm[e1 * 136 + c];
                float2 v0, v1;
                v0.x = clipf(acc[mf][nf][0] + q0.x);
                v0.y = clipf(acc[mf][nf][1] + q0.y);
                v1.x = clipf(acc[mf][nf][2] + q1.x);
                v1.y = clipf(acc[mf][nf][3] + q1.y);
                *(float2*)&Hs[rb * 136 + c]       = v0;
                *(float2*)&Hs[(rb + 8) * 136 + c] = v1;
            }
        }
        __syncthreads();

        // ---- stage D: pooling + linear head + sigmoid ----
        float contrib[8];
#pragma unroll
        for (int j = 0; j < 8; j++) {
            int el = half * 8 + j;
            float mx = -2.0f, mn = 2.0f, ss = 0.0f;
#pragma unroll
            for (int i = 0; i < 8; i++) {
                float h = Hs[(el * 8 + i) * 136 + d];
                mx = fmaxf(mx, h);
                mn = fminf(mn, h);
                ss += h * h;
            }
            contrib[j] = (mx - mn) * lw0 + sqrtf(ss * 0.125f) * lw1;
        }
#pragma unroll
        for (int j = 0; j < 8; j++) {
            float v = contrib[j];
            v += __shfl_xor_sync(0xffffffffu, v, 16);
            v += __shfl_xor_sync(0xffffffffu, v, 8);
            v += __shfl_xor_sync(0xffffffffu, v, 4);
            v += __shfl_xor_sync(0xffffffffu, v, 2);
            v += __shfl_xor_sync(0xffffffffu, v, 1);
            if (lane == 0) red[(half * 8 + j) * 4 + (w & 3)] = v;
        }
        __syncthreads();
        if (t < 16) {
            int e = ebase + t;
            if (e < E) {
                float* r = red + t * 4;
                float logit = r[0] + r[1] + r[2] + r[3] + lb;
                out[e] = 1.0f / (1.0f + expf(-logit));
            }
        }
        __syncthreads();   // protect smem before next iteration
    }
}

// ---------------------------------------------------------------------------
extern "C" void kernel_launch(void* const* d_in, const int* in_sizes, int n_in,
                              void* d_out, int out_size) {
    const float* pos   = (const float*)d_in[0];
    const float* Wenc  = (const float*)d_in[1];
    const float* benc  = (const float*)d_in[2];
    const float* gam   = (const float*)d_in[3];
    const float* bet   = (const float*)d_in[4];
    const float* alp   = (const float*)d_in[5];
    const float* chebW = (const float*)d_in[6];
    const float* chebb = (const float*)d_in[7];
    const float* linW  = (const float*)d_in[8];
    const float* linb  = (const float*)d_in[9];
    const int*   membs = (const int*)d_in[10];

    int N = in_sizes[0] / FDIM;   // 50000
    int E = in_sizes[10] / 8;     // 20000

    cudaFuncSetAttribute(encoder_cp, cudaFuncAttributeMaxDynamicSharedMemorySize,
                         ENC_SMEM);
    encoder_cp<<<(N + 127) / 128, 256, ENC_SMEM>>>(pos, Wenc, benc, N);

    cudaFuncSetAttribute(edge_mma, cudaFuncAttributeMaxDynamicSharedMemorySize,
                         ESMEM);
    int nIter = (E + 15) / 16;
    int grid = nIter < 148 ? nIter : 148;
    edge_mma<<<grid, 256, ESMEM>>>(membs, chebW, gam, bet, alp, chebb, linW,
                                   linb, (float*)d_out, E);
}

// round 6
// speedup vs baseline: 4.0469x; 1.0165x over previous
#include <cuda_runtime.h>
#include <math.h>
#include <stdint.h>

#define FDIM 512
#define DDIM 128
#define NMAX 50048
#define EPSF 1e-5f

// Scratch (allocation-free rule: device globals)
__device__ float g_x[(size_t)NMAX * DDIM];      // encoded node features

__device__ __forceinline__ unsigned f2tf(float x) {
    unsigned r; asm("cvt.rna.tf32.f32 %0, %1;" : "=r"(r) : "f"(x)); return r;
}
__device__ __forceinline__ void mma8(float* c, unsigned a0, unsigned a1,
                                     unsigned a2, unsigned a3,
                                     unsigned b0, unsigned b1) {
    asm volatile(
        "mma.sync.aligned.m16n8k8.row.col.f32.tf32.tf32.f32 "
        "{%0,%1,%2,%3},{%4,%5,%6,%7},{%8,%9},{%0,%1,%2,%3};"
        : "+f"(c[0]), "+f"(c[1]), "+f"(c[2]), "+f"(c[3])
        : "r"(a0), "r"(a1), "r"(a2), "r"(a3), "r"(b0), "r"(b1));
}
__device__ __forceinline__ float clipf(float v) {
    return fminf(1.0f, fmaxf(-1.0f, v));
}
__device__ __forceinline__ uint32_t smem_u32(const void* p) {
    uint32_t a;
    asm("{ .reg .u64 t; cvta.to.shared.u64 t, %1; cvt.u32.u64 %0, t; }"
        : "=r"(a) : "l"(p));
    return a;
}
__device__ __forceinline__ void cpasync16(uint32_t dst, const void* src, int szr) {
    asm volatile("cp.async.ca.shared.global [%0], [%1], 16, %2;"
                 :: "r"(dst), "l"(src), "r"(szr) : "memory");
}
#define CP_COMMIT() asm volatile("cp.async.commit_group;" ::: "memory")
#define CP_WAIT1()  asm volatile("cp.async.wait_group 1;" ::: "memory")

// ---------------------------------------------------------------------------
// Kernel 1: encoder  x = clip(pos @ W_enc + b, -1, 1) via tf32 mma.sync.
// (unchanged from R5 — controlled experiment: only edge kernel changes)
// ---------------------------------------------------------------------------
#define ENC_A_BYTES (128 * 20 * 4)                    // 10240
#define ENC_B_BYTES (16 * 128 * 4)                    // 8192
#define ENC_SMEM    (3 * (ENC_A_BYTES + ENC_B_BYTES)) // 55296

__global__ __launch_bounds__(256, 2)
void encoder_cp(const float* __restrict__ pos, const float* __restrict__ W,
                const float* __restrict__ bias, int N) {
    extern __shared__ unsigned char sm[];
    const uint32_t smb = smem_u32(sm);

    const int t = threadIdx.x, lane = t & 31, w = t >> 5;
    const int wy = w >> 1, wx = w & 1;
    const int lm = lane >> 2, lk = lane & 3;
    const int m0 = blockIdx.x * 128;

    const int ar0 = t >> 2, akq = t & 3;
    const int bk0 = t >> 5, bnq = t & 31;

    float acc[2][8][4];
#pragma unroll
    for (int mf = 0; mf < 2; mf++)
#pragma unroll
        for (int nf = 0; nf < 8; nf++)
#pragma unroll
            for (int r = 0; r < 4; r++) acc[mf][nf][r] = 0.0f;

    auto issue = [&](int s, int kt) {
        const uint32_t abase = smb + s * ENC_A_BYTES;
        const uint32_t bbase = smb + 3 * ENC_A_BYTES + s * ENC_B_BYTES;
#pragma unroll
        for (int h = 0; h < 2; h++) {
            int r = ar0 + h * 64;
            const float* src = pos + (size_t)(m0 + r) * FDIM + kt * 16 + akq * 4;
            uint32_t dst = abase + (r * 20 + akq * 4) * 4;
            cpasync16(dst, src, (m0 + r) < N ? 16 : 0);
        }
#pragma unroll
        for (int h = 0; h < 2; h++) {
            int k = bk0 + h * 8;
            const float* src = W + (size_t)(kt * 16 + k) * 128 + bnq * 4;
            uint32_t dst = bbase + (k * 128 + ((bnq * 4) ^ (8 * (k & 3)))) * 4;
            cpasync16(dst, src, 16);
        }
    };

    issue(0, 0); CP_COMMIT();
    issue(1, 1); CP_COMMIT();

    for (int kt = 0; kt < 32; kt++) {
        const int s = kt % 3;
        CP_WAIT1();
        __syncthreads();
        if (kt + 2 < 32) issue((kt + 2) % 3, kt + 2);
        CP_COMMIT();

        const unsigned* As = (const unsigned*)(sm + s * ENC_A_BYTES);
        const unsigned* Bs = (const unsigned*)(sm + 3 * ENC_A_BYTES + s * ENC_B_BYTES);
#pragma unroll
        for (int kh = 0; kh < 2; kh++) {
            const int k0 = kh * 8;
            unsigned a[2][4], b[8][2];
#pragma unroll
            for (int mf = 0; mf < 2; mf++) {
                int rb = wy * 32 + mf * 16;
                a[mf][0] = As[(rb + lm) * 20 + k0 + lk];
                a[mf][1] = As[(rb + lm + 8) * 20 + k0 + lk];
                a[mf][2] = As[(rb + lm) * 20 + k0 + lk + 4];
                a[mf][3] = As[(rb + lm + 8) * 20 + k0 + lk + 4];
            }
#pragma unroll
            for (int nf = 0; nf < 8; nf++) {
                int cb = wx * 64 + nf * 8;
                b[nf][0] = Bs[(k0 + lk) * 128 + ((cb + lm) ^ (8 * lk))];
                b[nf][1] = Bs[(k0 + lk + 4) * 128 + ((cb + lm) ^ (8 * lk))];
            }
#pragma unroll
            for (int mf = 0; mf < 2; mf++)
#pragma unroll
                for (int nf = 0; nf < 8; nf++)
                    mma8(acc[mf][nf], a[mf][0], a[mf][1], a[mf][2], a[mf][3],
                         b[nf][0], b[nf][1]);
        }
    }

#pragma unroll
    for (int mf = 0; mf < 2; mf++) {
        int r0 = m0 + wy * 32 + mf * 16 + lm;
#pragma unroll
        for (int nf = 0; nf < 8; nf++) {
            int c = wx * 64 + nf * 8 + 2 * lk;
            float b0 = __ldg(bias + c), b1 = __ldg(bias + c + 1);
            if (r0 < N) {
                float2 v;
                v.x = clipf(acc[mf][nf][0] + b0);
                v.y = clipf(acc[mf][nf][1] + b1);
                *(float2*)&g_x[(size_t)r0 * 128 + c] = v;
            }
            if (r0 + 8 < N) {
                float2 v;
                v.x = clipf(acc[mf][nf][2] + b0);
                v.y = clipf(acc[mf][nf][3] + b1);
                *(float2*)&g_x[(size_t)(r0 + 8) * 128 + c] = v;
            }
        }
    }
}

// ---------------------------------------------------------------------------
// Kernel 2: fused per-hyperedge pipeline, 16 edges/iter, tf32 mma.sync.
// R6: 512 threads (16 warps), warp tile 16x64 -> acc 32 regs, no spills.
// smem layout (dynamic, 218368 B): same as R5.
// ---------------------------------------------------------------------------
#define ESMEM 218368

__global__ __launch_bounds__(512, 1)
void edge_mma(const int* __restrict__ members, const float* __restrict__ chebW,
              const float* __restrict__ gamma_, const float* __restrict__ beta_,
              const float* __restrict__ alpha_, const float* __restrict__ chebb,
              const float* __restrict__ linW, const float* __restrict__ linb,
              float* __restrict__ out, int E) {
    extern __shared__ unsigned char esm[];
    unsigned* Acs = (unsigned*)esm;
    unsigned* Bcs = (unsigned*)(esm + 65536);
    unsigned* Gs  = (unsigned*)(esm + 131072);
    float*    Hs  = (float*)(esm + 131072);
    unsigned* Ssm = (unsigned*)(esm + 200704);
    float*    Qsm = (float*)(esm + 209408);
    float*    red = (float*)(esm + 218112);

    const int t = threadIdx.x;
    const int lane = t & 31, w = t >> 5;
    const int lm = lane >> 2, lk = lane & 3;

    // ---- fold of prep: A = W0 + W1/7 - 47/49 W2 ; B = -W1/7 + 12/49 W2 ----
    for (int i = t; i < 4096; i += 512) {
        int dd = i >> 5;
        int cg = (i & 31) * 4;
        const float* p0 = chebW + dd * 128 + cg;
        float4 w0 = __ldg((const float4*)(p0));
        float4 w1 = __ldg((const float4*)(p0 + 16384));
        float4 w2 = __ldg((const float4*)(p0 + 32768));
        int dst = dd * 128 + (cg ^ (8 * (dd & 3)));
        uint4 ua, ub;
        ua.x = f2tf(w0.x + w1.x * (1.0f/7.0f) - w2.x * (47.0f/49.0f));
        ua.y = f2tf(w0.y + w1.y * (1.0f/7.0f) - w2.y * (47.0f/49.0f));
        ua.z = f2tf(w0.z + w1.z * (1.0f/7.0f) - w2.z * (47.0f/49.0f));
        ua.w = f2tf(w0.w + w1.w * (1.0f/7.0f) - w2.w * (47.0f/49.0f));
        ub.x = f2tf(-w1.x * (1.0f/7.0f) + w2.x * (12.0f/49.0f));
        ub.y = f2tf(-w1.y * (1.0f/7.0f) + w2.y * (12.0f/49.0f));
        ub.z = f2tf(-w1.z * (1.0f/7.0f) + w2.z * (12.0f/49.0f));
        ub.w = f2tf(-w1.w * (1.0f/7.0f) + w2.w * (12.0f/49.0f));
        *(uint4*)&Acs[dst] = ua;
        *(uint4*)&Bcs[dst] = ub;
    }

    // stage A mapping: one edge per warp? no — one edge per thread-group:
    // el = t>>5 (warp id), channels 4*(t&31)
    const int c4 = t & 31;
    const float4 ga4 = *(const float4*)(gamma_ + 4 * c4);
    const float4 be4 = *(const float4*)(beta_  + 4 * c4);
    const float4 al4 = *(const float4*)(alpha_ + 4 * c4);

    // stage D mapping: d = t&127, quarter = t>>7 -> edges quarter*4..+4
    const int d = t & 127, quarter = t >> 7;
    const float lw0 = linW[d], lw1 = linW[128 + d];
    const float lb = __ldg(linb);

    // MMA mapping: 16 warps, warp tile 16 rows x 64 cols
    const int m0 = (w >> 1) * 16, n0 = (w & 1) * 64, nq0 = w * 8;
    const int nIter = (E + 15) >> 4;

    __syncthreads();   // Acs/Bcs ready

    for (int it = blockIdx.x; it < nIter; it += gridDim.x) {
        const int ebase = it * 16;

        // warp w handles edge el = w; lane<8 loads its member indices
        const int el = w;
        const int e = ebase + el;
        int mreg = 0;
        if (lane < 8 && e < E) mreg = __ldg(&members[e * 8 + lane]);

        // ---- stage A: gather + GraphNorm (4 channels x 1 edge / thread) ----
        {
            unsigned* grow = Gs + el * 8 * 132 + 4 * c4;
            unsigned* srow = Ssm + el * 132 + 4 * c4;
            if (e < E) {
                float4 xv[8];
#pragma unroll
                for (int i = 0; i < 8; i++) {
                    int node = __shfl_sync(0xffffffffu, mreg, i);
                    xv[i] = *(const float4*)(g_x + (size_t)node * 128 + 4 * c4);
                }
                float4 mean = make_float4(0, 0, 0, 0);
#pragma unroll
                for (int i = 0; i < 8; i++) {
                    mean.x += xv[i].x; mean.y += xv[i].y;
                    mean.z += xv[i].z; mean.w += xv[i].w;
                }
                mean.x *= 0.125f; mean.y *= 0.125f;
                mean.z *= 0.125f; mean.w *= 0.125f;
                float4 am = make_float4(al4.x * mean.x, al4.y * mean.y,
                                        al4.z * mean.z, al4.w * mean.w);
                float4 var = make_float4(0, 0, 0, 0);
#pragma unroll
                for (int i = 0; i < 8; i++) {
                    xv[i].x -= am.x; xv[i].y -= am.y;
                    xv[i].z -= am.z; xv[i].w -= am.w;
                    var.x += xv[i].x * xv[i].x; var.y += xv[i].y * xv[i].y;
                    var.z += xv[i].z * xv[i].z; var.w += xv[i].w * xv[i].w;
                }
                float4 inv;
                inv.x = ga4.x * rsqrtf(var.x * 0.125f + EPSF);
                inv.y = ga4.y * rsqrtf(var.y * 0.125f + EPSF);
                inv.z = ga4.z * rsqrtf(var.z * 0.125f + EPSF);
                inv.w = ga4.w * rsqrtf(var.w * 0.125f + EPSF);
#pragma unroll
                for (int i = 0; i < 8; i++) {
                    uint4 u;
                    u.x = f2tf(xv[i].x * inv.x + be4.x);
                    u.y = f2tf(xv[i].y * inv.y + be4.y);
                    u.z = f2tf(xv[i].z * inv.z + be4.z);
                    u.w = f2tf(xv[i].w * inv.w + be4.w);
                    *(uint4*)(grow + i * 132) = u;
                }
                uint4 su;
                su.x = f2tf(inv.x * 8.0f * mean.x * (1.0f - al4.x) + 8.0f * be4.x);
                su.y = f2tf(inv.y * 8.0f * mean.y * (1.0f - al4.y) + 8.0f * be4.y);
                su.z = f2tf(inv.z * 8.0f * mean.z * (1.0f - al4.z) + 8.0f * be4.z);
                su.w = f2tf(inv.w * 8.0f * mean.w * (1.0f - al4.w) + 8.0f * be4.w);
                *(uint4*)srow = su;
            } else {
                uint4 z = make_uint4(0, 0, 0, 0);
#pragma unroll
                for (int i = 0; i < 8; i++) *(uint4*)(grow + i * 132) = z;
                *(uint4*)srow = z;
            }
        }
        __syncthreads();

        // ---- stage B: MMAs. main: g[128,128]@A ; q: S[16,128]@B ----
        float acc[8][4];
        float qac[4];
#pragma unroll
        for (int nf = 0; nf < 8; nf++)
#pragma unroll
            for (int r = 0; r < 4; r++) acc[nf][r] = 0.0f;
#pragma unroll
        for (int r = 0; r < 4; r++) qac[r] = 0.0f;

#pragma unroll
        for (int ks = 0; ks < 16; ks++) {
            const int k0 = ks * 8;
            const int sw = 8 * lk;
            unsigned a0 = Gs[(m0 + lm) * 132 + k0 + lk];
            unsigned a1 = Gs[(m0 + lm + 8) * 132 + k0 + lk];
            unsigned a2 = Gs[(m0 + lm) * 132 + k0 + lk + 4];
            unsigned a3 = Gs[(m0 + lm + 8) * 132 + k0 + lk + 4];
            unsigned b[8][2];
#pragma unroll
            for (int nf = 0; nf < 8; nf++) {
                int cb = n0 + nf * 8;
                b[nf][0] = Acs[(k0 + lk) * 128 + ((cb + lm) ^ sw)];
                b[nf][1] = Acs[(k0 + lk + 4) * 128 + ((cb + lm) ^ sw)];
            }
#pragma unroll
            for (int nf = 0; nf < 8; nf++)
                mma8(acc[nf], a0, a1, a2, a3, b[nf][0], b[nf][1]);
            unsigned sa0 = Ssm[lm * 132 + k0 + lk];
            unsigned sa1 = Ssm[(lm + 8) * 132 + k0 + lk];
            unsigned sa2 = Ssm[lm * 132 + k0 + lk + 4];
            unsigned sa3 = Ssm[(lm + 8) * 132 + k0 + lk + 4];
            unsigned qb0 = Bcs[(k0 + lk) * 128 + ((nq0 + lm) ^ sw)];
            unsigned qb1 = Bcs[(k0 + lk + 4) * 128 + ((nq0 + lm) ^ sw)];
            mma8(qac, sa0, sa1, sa2, sa3, qb0, qb1);
        }
        // write Qsm (+chebb folded in)
        {
            int c = nq0 + 2 * lk;
            float cb0 = __ldg(chebb + c), cb1 = __ldg(chebb + c + 1);
            Qsm[lm * 136 + c]           = qac[0] + cb0;
            Qsm[lm * 136 + c + 1]       = qac[1] + cb1;
            Qsm[(lm + 8) * 136 + c]     = qac[2] + cb0;
            Qsm[(lm + 8) * 136 + c + 1] = qac[3] + cb1;
        }
        __syncthreads();

        // ---- stage C: h = clip(acc + Q[e][c]) -> Hs (reuses Gs space) ----
        {
            int rb = m0 + lm;
            int e0 = rb >> 3;
            int e1 = (rb + 8) >> 3;
#pragma unroll
            for (int nf = 0; nf < 8; nf++) {
                int c = n0 + nf * 8 + 2 * lk;
                float2 q0 = *(const float2*)&Qsm[e0 * 136 + c];
                float2 q1 = *(const float2*)&Qsm[e1 * 136 + c];
                float2 v0, v1;
                v0.x = clipf(acc[nf][0] + q0.x);
                v0.y = clipf(acc[nf][1] + q0.y);
                v1.x = clipf(acc[nf][2] + q1.x);
                v1.y = clipf(acc[nf][3] + q1.y);
                *(float2*)&Hs[rb * 136 + c]       = v0;
                *(float2*)&Hs[(rb + 8) * 136 + c] = v1;
            }
        }
        __syncthreads();

        // ---- stage D: pooling + linear head + sigmoid (4 edges / thread) ----
        float contrib[4];
#pragma unroll
        for (int j = 0; j < 4; j++) {
            int elj = quarter * 4 + j;
            float mx = -2.0f, mn = 2.0f, ss = 0.0f;
#pragma unroll
            for (int i = 0; i < 8; i++) {
                float h = Hs[(elj * 8 + i) * 136 + d];
                mx = fmaxf(mx, h);
                mn = fminf(mn, h);
                ss += h * h;
            }
            contrib[j] = (mx - mn) * lw0 + sqrtf(ss * 0.125f) * lw1;
        }
#pragma unroll
        for (int j = 0; j < 4; j++) {
            float v = contrib[j];
            v += __shfl_xor_sync(0xffffffffu, v, 16);
            v += __shfl_xor_sync(0xffffffffu, v, 8);
            v += __shfl_xor_sync(0xffffffffu, v, 4);
            v += __shfl_xor_sync(0xffffffffu, v, 2);
            v += __shfl_xor_sync(0xffffffffu, v, 1);
            if (lane == 0) red[(quarter * 4 + j) * 4 + (w & 3)] = v;
        }
        __syncthreads();
        if (t < 16) {
            int eo = ebase + t;
            if (eo < E) {
                float* r = red + t * 4;
                float logit = r[0] + r[1] + r[2] + r[3] + lb;
                out[eo] = 1.0f / (1.0f + expf(-logit));
            }
        }
        __syncthreads();   // protect smem before next iteration
    }
}

// ---------------------------------------------------------------------------
extern "C" void kernel_launch(void* const* d_in, const int* in_sizes, int n_in,
                              void* d_out, int out_size) {
    const float* pos   = (const float*)d_in[0];
    const float* Wenc  = (const float*)d_in[1];
    const float* benc  = (const float*)d_in[2];
    const float* gam   = (const float*)d_in[3];
    const float* bet   = (const float*)d_in[4];
    const float* alp   = (const float*)d_in[5];
    const float* chebW = (const float*)d_in[6];
    const float* chebb = (const float*)d_in[7];
    const float* linW  = (const float*)d_in[8];
    const float* linb  = (const float*)d_in[9];
    const int*   membs = (const int*)d_in[10];

    int N = in_sizes[0] / FDIM;   // 50000
    int E = in_sizes[10] / 8;     // 20000

    cudaFuncSetAttribute(encoder_cp, cudaFuncAttributeMaxDynamicSharedMemorySize,
                         ENC_SMEM);
    encoder_cp<<<(N + 127) / 128, 256, ENC_SMEM>>>(pos, Wenc, benc, N);

    cudaFuncSetAttribute(edge_mma, cudaFuncAttributeMaxDynamicSharedMemorySize,
                         ESMEM);
    int nIter = (E + 15) / 16;
    int grid = nIter < 148 ? nIter : 148;
    edge_mma<<<grid, 512, ESMEM>>>(membs, chebW, gam, bet, alp, chebb, linW,
                                   linb, (float*)d_out, E);
}

// round 7
// speedup vs baseline: 5.0205x; 1.2406x over previous
#include <cuda_runtime.h>
#include <cuda_fp16.h>
#include <math.h>
#include <stdint.h>

#define FDIM 512
#define DDIM 128
#define NMAX 50048
#define EPSF 1e-5f

// Scratch (allocation-free rule: device globals)
__device__ float g_x[(size_t)NMAX * DDIM];      // encoded node features

__device__ __forceinline__ unsigned f2tf(float x) {
    unsigned r; asm("cvt.rna.tf32.f32 %0, %1;" : "=r"(r) : "f"(x)); return r;
}
__device__ __forceinline__ void mma8(float* c, unsigned a0, unsigned a1,
                                     unsigned a2, unsigned a3,
                                     unsigned b0, unsigned b1) {
    asm volatile(
        "mma.sync.aligned.m16n8k8.row.col.f32.tf32.tf32.f32 "
        "{%0,%1,%2,%3},{%4,%5,%6,%7},{%8,%9},{%0,%1,%2,%3};"
        : "+f"(c[0]), "+f"(c[1]), "+f"(c[2]), "+f"(c[3])
        : "r"(a0), "r"(a1), "r"(a2), "r"(a3), "r"(b0), "r"(b1));
}
__device__ __forceinline__ void mma16h(float* c, unsigned a0, unsigned a1,
                                       unsigned a2, unsigned a3,
                                       unsigned b0, unsigned b1) {
    asm volatile(
        "mma.sync.aligned.m16n8k16.row.col.f32.f16.f16.f32 "
        "{%0,%1,%2,%3},{%4,%5,%6,%7},{%8,%9},{%0,%1,%2,%3};"
        : "+f"(c[0]), "+f"(c[1]), "+f"(c[2]), "+f"(c[3])
        : "r"(a0), "r"(a1), "r"(a2), "r"(a3), "r"(b0), "r"(b1));
}
__device__ __forceinline__ float clipf(float v) {
    return fminf(1.0f, fmaxf(-1.0f, v));
}
__device__ __forceinline__ unsigned pack2h(float lo, float hi) {
    __half2 h = __floats2half2_rn(lo, hi);
    return *(unsigned*)&h;
}
__device__ __forceinline__ uint32_t smem_u32(const void* p) {
    uint32_t a;
    asm("{ .reg .u64 t; cvta.to.shared.u64 t, %1; cvt.u32.u64 %0, t; }"
        : "=r"(a) : "l"(p));
    return a;
}
__device__ __forceinline__ void cpasync16(uint32_t dst, const void* src, int szr) {
    asm volatile("cp.async.ca.shared.global [%0], [%1], 16, %2;"
                 :: "r"(dst), "l"(src), "r"(szr) : "memory");
}
#define CP_COMMIT() asm volatile("cp.async.commit_group;" ::: "memory")
#define CP_WAIT1()  asm volatile("cp.async.wait_group 1;" ::: "memory")

// ---------------------------------------------------------------------------
// Kernel 1: encoder  x = clip(pos @ W_enc + b, -1, 1) via tf32 mma.sync.
// (unchanged from R6 — controlled experiment: only edge kernel changes)
// ---------------------------------------------------------------------------
#define ENC_A_BYTES (128 * 20 * 4)                    // 10240
#define ENC_B_BYTES (16 * 128 * 4)                    // 8192
#define ENC_SMEM    (3 * (ENC_A_BYTES + ENC_B_BYTES)) // 55296

__global__ __launch_bounds__(256, 2)
void encoder_cp(const float* __restrict__ pos, const float* __restrict__ W,
                const float* __restrict__ bias, int N) {
    extern __shared__ unsigned char sm[];
    const uint32_t smb = smem_u32(sm);

    const int t = threadIdx.x, lane = t & 31, w = t >> 5;
    const int wy = w >> 1, wx = w & 1;
    const int lm = lane >> 2, lk = lane & 3;
    const int m0 = blockIdx.x * 128;

    const int ar0 = t >> 2, akq = t & 3;
    const int bk0 = t >> 5, bnq = t & 31;

    float acc[2][8][4];
#pragma unroll
    for (int mf = 0; mf < 2; mf++)
#pragma unroll
        for (int nf = 0; nf < 8; nf++)
#pragma unroll
            for (int r = 0; r < 4; r++) acc[mf][nf][r] = 0.0f;

    auto issue = [&](int s, int kt) {
        const uint32_t abase = smb + s * ENC_A_BYTES;
        const uint32_t bbase = smb + 3 * ENC_A_BYTES + s * ENC_B_BYTES;
#pragma unroll
        for (int h = 0; h < 2; h++) {
            int r = ar0 + h * 64;
            const float* src = pos + (size_t)(m0 + r) * FDIM + kt * 16 + akq * 4;
            uint32_t dst = abase + (r * 20 + akq * 4) * 4;
            cpasync16(dst, src, (m0 + r) < N ? 16 : 0);
        }
#pragma unroll
        for (int h = 0; h < 2; h++) {
            int k = bk0 + h * 8;
            const float* src = W + (size_t)(kt * 16 + k) * 128 + bnq * 4;
            uint32_t dst = bbase + (k * 128 + ((bnq * 4) ^ (8 * (k & 3)))) * 4;
            cpasync16(dst, src, 16);
        }
    };

    issue(0, 0); CP_COMMIT();
    issue(1, 1); CP_COMMIT();

    for (int kt = 0; kt < 32; kt++) {
        const int s = kt % 3;
        CP_WAIT1();
        __syncthreads();
        if (kt + 2 < 32) issue((kt + 2) % 3, kt + 2);
        CP_COMMIT();

        const unsigned* As = (const unsigned*)(sm + s * ENC_A_BYTES);
        const unsigned* Bs = (const unsigned*)(sm + 3 * ENC_A_BYTES + s * ENC_B_BYTES);
#pragma unroll
        for (int kh = 0; kh < 2; kh++) {
            const int k0 = kh * 8;
            unsigned a[2][4], b[8][2];
#pragma unroll
            for (int mf = 0; mf < 2; mf++) {
                int rb = wy * 32 + mf * 16;
                a[mf][0] = As[(rb + lm) * 20 + k0 + lk];
                a[mf][1] = As[(rb + lm + 8) * 20 + k0 + lk];
                a[mf][2] = As[(rb + lm) * 20 + k0 + lk + 4];
                a[mf][3] = As[(rb + lm + 8) * 20 + k0 + lk + 4];
            }
#pragma unroll
            for (int nf = 0; nf < 8; nf++) {
                int cb = wx * 64 + nf * 8;
                b[nf][0] = Bs[(k0 + lk) * 128 + ((cb + lm) ^ (8 * lk))];
                b[nf][1] = Bs[(k0 + lk + 4) * 128 + ((cb + lm) ^ (8 * lk))];
            }
#pragma unroll
            for (int mf = 0; mf < 2; mf++)
#pragma unroll
                for (int nf = 0; nf < 8; nf++)
                    mma8(acc[mf][nf], a[mf][0], a[mf][1], a[mf][2], a[mf][3],
                         b[nf][0], b[nf][1]);
        }
    }

#pragma unroll
    for (int mf = 0; mf < 2; mf++) {
        int r0 = m0 + wy * 32 + mf * 16 + lm;
#pragma unroll
        for (int nf = 0; nf < 8; nf++) {
            int c = wx * 64 + nf * 8 + 2 * lk;
            float b0 = __ldg(bias + c), b1 = __ldg(bias + c + 1);
            if (r0 < N) {
                float2 v;
                v.x = clipf(acc[mf][nf][0] + b0);
                v.y = clipf(acc[mf][nf][1] + b1);
                *(float2*)&g_x[(size_t)r0 * 128 + c] = v;
            }
            if (r0 + 8 < N) {
                float2 v;
                v.x = clipf(acc[mf][nf][2] + b0);
                v.y = clipf(acc[mf][nf][3] + b1);
                *(float2*)&g_x[(size_t)(r0 + 8) * 128 + c] = v;
            }
        }
    }
}

// ---------------------------------------------------------------------------
// Kernel 2: fused per-hyperedge pipeline, 16 edges/iter, FP16 mma m16n8k16.
// R7: operands fp16 (word = packed k-pair), 8 k-steps, warp tile 32x32.
// smem layout (dynamic, 148480 B):
//   Acs  word[64*128] @0       : Cheb A fp16, [k2][n] XOR-8(k2&3) swizzle
//   Bcs  word[64*128] @32768   : Cheb B fp16
//   Gw   word[128*68] @65536   : g fp16, [row][k2], stride 68 words
//   Hs   float[128*136]@65536  : (union w/ Gw) h fp32, stride 136
//   Sw   word[16*68]  @135168  : S fp16
//   Qsm  float[16*136]@139520  : q = S@B + chebb
//   red  float[16*4]  @148224
// ---------------------------------------------------------------------------
#define ESMEM 148480

__global__ __launch_bounds__(512, 1)
void edge_mma(const int* __restrict__ members, const float* __restrict__ chebW,
              const float* __restrict__ gamma_, const float* __restrict__ beta_,
              const float* __restrict__ alpha_, const float* __restrict__ chebb,
              const float* __restrict__ linW, const float* __restrict__ linb,
              float* __restrict__ out, int E) {
    extern __shared__ unsigned char esm[];
    unsigned* Acs = (unsigned*)esm;
    unsigned* Bcs = (unsigned*)(esm + 32768);
    unsigned* Gw  = (unsigned*)(esm + 65536);
    float*    Hs  = (float*)(esm + 65536);
    unsigned* Sw  = (unsigned*)(esm + 135168);
    float*    Qsm = (float*)(esm + 139520);
    float*    red = (float*)(esm + 148224);

    const int t = threadIdx.x;
    const int lane = t & 31, w = t >> 5;
    const int lm = lane >> 2, lk = lane & 3;

    // ---- fold of prep: A = W0 + W1/7 - 47/49 W2 ; B = -W1/7 + 12/49 W2 ----
    // word(k2, n) packs rows d=2k2 (lo) and d=2k2+1 (hi), fp16.
    for (int i = t; i < 2048; i += 512) {
        int k2 = i >> 5;
        int cg = (i & 31) * 4;
        const float* p0 = chebW + (2 * k2) * 128 + cg;       // row d=2k2
        const float* p1 = p0 + 128;                           // row d=2k2+1
        float4 w00 = __ldg((const float4*)(p0));
        float4 w01 = __ldg((const float4*)(p0 + 16384));
        float4 w02 = __ldg((const float4*)(p0 + 32768));
        float4 w10 = __ldg((const float4*)(p1));
        float4 w11 = __ldg((const float4*)(p1 + 16384));
        float4 w12 = __ldg((const float4*)(p1 + 32768));
        float a0[4] = {w00.x + w01.x*(1.0f/7.0f) - w02.x*(47.0f/49.0f),
                       w00.y + w01.y*(1.0f/7.0f) - w02.y*(47.0f/49.0f),
                       w00.z + w01.z*(1.0f/7.0f) - w02.z*(47.0f/49.0f),
                       w00.w + w01.w*(1.0f/7.0f) - w02.w*(47.0f/49.0f)};
        float a1[4] = {w10.x + w11.x*(1.0f/7.0f) - w12.x*(47.0f/49.0f),
                       w10.y + w11.y*(1.0f/7.0f) - w12.y*(47.0f/49.0f),
                       w10.z + w11.z*(1.0f/7.0f) - w12.z*(47.0f/49.0f),
                       w10.w + w11.w*(1.0f/7.0f) - w12.w*(47.0f/49.0f)};
        float b0[4] = {-w01.x*(1.0f/7.0f) + w02.x*(12.0f/49.0f),
                       -w01.y*(1.0f/7.0f) + w02.y*(12.0f/49.0f),
                       -w01.z*(1.0f/7.0f) + w02.z*(12.0f/49.0f),
                       -w01.w*(1.0f/7.0f) + w02.w*(12.0f/49.0f)};
        float b1[4] = {-w11.x*(1.0f/7.0f) + w12.x*(12.0f/49.0f),
                       -w11.y*(1.0f/7.0f) + w12.y*(12.0f/49.0f),
                       -w11.z*(1.0f/7.0f) + w12.z*(12.0f/49.0f),
                       -w11.w*(1.0f/7.0f) + w12.w*(12.0f/49.0f)};
        int dst = k2 * 128 + (cg ^ (8 * (k2 & 3)));
        uint4 ua = make_uint4(pack2h(a0[0], a1[0]), pack2h(a0[1], a1[1]),
                              pack2h(a0[2], a1[2]), pack2h(a0[3], a1[3]));
        uint4 ub = make_uint4(pack2h(b0[0], b1[0]), pack2h(b0[1], b1[1]),
                              pack2h(b0[2], b1[2]), pack2h(b0[3], b1[3]));
        *(uint4*)&Acs[dst] = ua;
        *(uint4*)&Bcs[dst] = ub;
    }

    // stage A mapping: warp w = edge w; channels 4*(t&31)
    const int c4 = t & 31;
    const float4 ga4 = *(const float4*)(gamma_ + 4 * c4);
    const float4 be4 = *(const float4*)(beta_  + 4 * c4);
    const float4 al4 = *(const float4*)(alpha_ + 4 * c4);

    // stage D mapping
    const int d = t & 127, quarter = t >> 7;
    const float lw0 = linW[d], lw1 = linW[128 + d];
    const float lb = __ldg(linb);

    // MMA mapping: 16 warps, warp tile 32x32
    const int m0 = (w >> 2) * 32, n0 = (w & 3) * 32, nq0 = w * 8;
    const int nIter = (E + 15) >> 4;

    __syncthreads();   // Acs/Bcs ready

    for (int it = blockIdx.x; it < nIter; it += gridDim.x) {
        const int ebase = it * 16;

        const int el = w;
        const int e = ebase + el;
        int mreg = 0;
        if (lane < 8 && e < E) mreg = __ldg(&members[e * 8 + lane]);

        // ---- stage A: gather + GraphNorm -> fp16 Gw / Sw ----
        {
            unsigned* grow = Gw + el * 8 * 68 + 2 * c4;
            unsigned* srow = Sw + el * 68 + 2 * c4;
            if (e < E) {
                float4 xv[8];
#pragma unroll
                for (int i = 0; i < 8; i++) {
                    int node = __shfl_sync(0xffffffffu, mreg, i);
                    xv[i] = *(const float4*)(g_x + (size_t)node * 128 + 4 * c4);
                }
                float4 mean = make_float4(0, 0, 0, 0);
#pragma unroll
                for (int i = 0; i < 8; i++) {
                    mean.x += xv[i].x; mean.y += xv[i].y;
                    mean.z += xv[i].z; mean.w += xv[i].w;
                }
                mean.x *= 0.125f; mean.y *= 0.125f;
                mean.z *= 0.125f; mean.w *= 0.125f;
                float4 am = make_float4(al4.x * mean.x, al4.y * mean.y,
                                        al4.z * mean.z, al4.w * mean.w);
                float4 var = make_float4(0, 0, 0, 0);
#pragma unroll
                for (int i = 0; i < 8; i++) {
                    xv[i].x -= am.x; xv[i].y -= am.y;
                    xv[i].z -= am.z; xv[i].w -= am.w;
                    var.x += xv[i].x * xv[i].x; var.y += xv[i].y * xv[i].y;
                    var.z += xv[i].z * xv[i].z; var.w += xv[i].w * xv[i].w;
                }
                float4 inv;
                inv.x = ga4.x * rsqrtf(var.x * 0.125f + EPSF);
                inv.y = ga4.y * rsqrtf(var.y * 0.125f + EPSF);
                inv.z = ga4.z * rsqrtf(var.z * 0.125f + EPSF);
                inv.w = ga4.w * rsqrtf(var.w * 0.125f + EPSF);
#pragma unroll
                for (int i = 0; i < 8; i++) {
                    uint2 u;
                    u.x = pack2h(xv[i].x * inv.x + be4.x, xv[i].y * inv.y + be4.y);
                    u.y = pack2h(xv[i].z * inv.z + be4.z, xv[i].w * inv.w + be4.w);
                    *(uint2*)(grow + i * 68) = u;
                }
                uint2 su;
                su.x = pack2h(inv.x * 8.0f * mean.x * (1.0f - al4.x) + 8.0f * be4.x,
                              inv.y * 8.0f * mean.y * (1.0f - al4.y) + 8.0f * be4.y);
                su.y = pack2h(inv.z * 8.0f * mean.z * (1.0f - al4.z) + 8.0f * be4.z,
                              inv.w * 8.0f * mean.w * (1.0f - al4.w) + 8.0f * be4.w);
                *(uint2*)srow = su;
            } else {
                uint2 z = make_uint2(0, 0);
#pragma unroll
                for (int i = 0; i < 8; i++) *(uint2*)(grow + i * 68) = z;
                *(uint2*)srow = z;
            }
        }
        __syncthreads();

        // ---- stage B: fp16 MMAs. main: g[128,128]@A ; q: S[16,128]@B ----
        float acc[2][4][4];
        float qac[4];
#pragma unroll
        for (int mf = 0; mf < 2; mf++)
#pragma unroll
            for (int nf = 0; nf < 4; nf++)
#pragma unroll
                for (int r = 0; r < 4; r++) acc[mf][nf][r] = 0.0f;
#pragma unroll
        for (int r = 0; r < 4; r++) qac[r] = 0.0f;

#pragma unroll
        for (int ks = 0; ks < 8; ks++) {
            const int k20 = ks * 8;
            const int sw = 8 * lk;
            unsigned a[2][4];
#pragma unroll
            for (int mf = 0; mf < 2; mf++) {
                int rb = m0 + mf * 16;
                a[mf][0] = Gw[(rb + lm) * 68 + k20 + lk];
                a[mf][1] = Gw[(rb + lm + 8) * 68 + k20 + lk];
                a[mf][2] = Gw[(rb + lm) * 68 + k20 + lk + 4];
                a[mf][3] = Gw[(rb + lm + 8) * 68 + k20 + lk + 4];
            }
            unsigned b[4][2];
#pragma unroll
            for (int nf = 0; nf < 4; nf++) {
                int cb = n0 + nf * 8;
                b[nf][0] = Acs[(k20 + lk) * 128 + ((cb + lm) ^ sw)];
                b[nf][1] = Acs[(k20 + lk + 4) * 128 + ((cb + lm) ^ sw)];
            }
#pragma unroll
            for (int mf = 0; mf < 2; mf++)
#pragma unroll
                for (int nf = 0; nf < 4; nf++)
                    mma16h(acc[mf][nf], a[mf][0], a[mf][1], a[mf][2], a[mf][3],
                           b[nf][0], b[nf][1]);
            unsigned sa0 = Sw[lm * 68 + k20 + lk];
            unsigned sa1 = Sw[(lm + 8) * 68 + k20 + lk];
            unsigned sa2 = Sw[lm * 68 + k20 + lk + 4];
            unsigned sa3 = Sw[(lm + 8) * 68 + k20 + lk + 4];
            unsigned qb0 = Bcs[(k20 + lk) * 128 + ((nq0 + lm) ^ sw)];
            unsigned qb1 = Bcs[(k20 + lk + 4) * 128 + ((nq0 + lm) ^ sw)];
            mma16h(qac, sa0, sa1, sa2, sa3, qb0, qb1);
        }
        // write Qsm (+chebb folded in)
        {
            int c = nq0 + 2 * lk;
            float cb0 = __ldg(chebb + c), cb1 = __ldg(chebb + c + 1);
            Qsm[lm * 136 + c]           = qac[0] + cb0;
            Qsm[lm * 136 + c + 1]       = qac[1] + cb1;
            Qsm[(lm + 8) * 136 + c]     = qac[2] + cb0;
            Qsm[(lm + 8) * 136 + c + 1] = qac[3] + cb1;
        }
        __syncthreads();

        // ---- stage C: h = clip(acc + Q[e][c]) -> Hs (reuses Gw space) ----
#pragma unroll
        for (int mf = 0; mf < 2; mf++) {
            int rb = m0 + mf * 16 + lm;
            int e0 = rb >> 3;
            int e1 = (rb + 8) >> 3;
#pragma unroll
            for (int nf = 0; nf < 4; nf++) {
                int c = n0 + nf * 8 + 2 * lk;
                float2 q0 = *(const float2*)&Qsm[e0 * 136 + c];
                float2 q1 = *(const float2*)&Qsm[e1 * 136 + c];
                float2 v0, v1;
                v0.x = clipf(acc[mf][nf][0] + q0.x);
                v0.y = clipf(acc[mf][nf][1] + q0.y);
                v1.x = clipf(acc[mf][nf][2] + q1.x);
                v1.y = clipf(acc[mf][nf][3] + q1.y);
                *(float2*)&Hs[rb * 136 + c]       = v0;
                *(float2*)&Hs[(rb + 8) * 136 + c] = v1;
            }
        }
        __syncthreads();

        // ---- stage D: pooling + linear head + sigmoid (4 edges / thread) ----
        float contrib[4];
#pragma unroll
        for (int j = 0; j < 4; j++) {
            int elj = quarter * 4 + j;
            float mx = -2.0f, mn = 2.0f, ss = 0.0f;
#pragma unroll
            for (int i = 0; i < 8; i++) {
                float h = Hs[(elj * 8 + i) * 136 + d];
                mx = fmaxf(mx, h);
                mn = fminf(mn, h);
                ss += h * h;
            }
            contrib[j] = (mx - mn) * lw0 + sqrtf(ss * 0.125f) * lw1;
        }
#pragma unroll
        for (int j = 0; j < 4; j++) {
            float v = contrib[j];
            v += __shfl_xor_sync(0xffffffffu, v, 16);
            v += __shfl_xor_sync(0xffffffffu, v, 8);
            v += __shfl_xor_sync(0xffffffffu, v, 4);
            v += __shfl_xor_sync(0xffffffffu, v, 2);
            v += __shfl_xor_sync(0xffffffffu, v, 1);
            if (lane == 0) red[(quarter * 4 + j) * 4 + (w & 3)] = v;
        }
        __syncthreads();
        if (t < 16) {
            int eo = ebase + t;
            if (eo < E) {
                float* r = red + t * 4;
                float logit = r[0] + r[1] + r[2] + r[3] + lb;
                out[eo] = 1.0f / (1.0f + expf(-logit));
            }
        }
        __syncthreads();   // protect smem before next iteration
    }
}

// ---------------------------------------------------------------------------
extern "C" void kernel_launch(void* const* d_in, const int* in_sizes, int n_in,
                              void* d_out, int out_size) {
    const float* pos   = (const float*)d_in[0];
    const float* Wenc  = (const float*)d_in[1];
    const float* benc  = (const float*)d_in[2];
    const float* gam   = (const float*)d_in[3];
    const float* bet   = (const float*)d_in[4];
    const float* alp   = (const float*)d_in[5];
    const float* chebW = (const float*)d_in[6];
    const float* chebb = (const float*)d_in[7];
    const float* linW  = (const float*)d_in[8];
    const float* linb  = (const float*)d_in[9];
    const int*   membs = (const int*)d_in[10];

    int N = in_sizes[0] / FDIM;   // 50000
    int E = in_sizes[10] / 8;     // 20000

    cudaFuncSetAttribute(encoder_cp, cudaFuncAttributeMaxDynamicSharedMemorySize,
                         ENC_SMEM);
    encoder_cp<<<(N + 127) / 128, 256, ENC_SMEM>>>(pos, Wenc, benc, N);

    cudaFuncSetAttribute(edge_mma, cudaFuncAttributeMaxDynamicSharedMemorySize,
                         ESMEM);
    int nIter = (E + 15) / 16;
    int grid = nIter < 148 ? nIter : 148;
    edge_mma<<<grid, 512, ESMEM>>>(membs, chebW, gam, bet, alp, chebb, linW,
                                   linb, (float*)d_out, E);
}